// round 13
// baseline (speedup 1.0000x reference)
#include <cuda_runtime.h>
#include <cuda_bf16.h>
#include <math.h>
#include <stdint.h>

// Problem constants
#define BB   4
#define NQ   1024
#define MM   512
#define DD   512
#define PP   256
#define HH   8
#define DH   64
#define LL   6
#define FFI  2048
#define RR   (BB*NQ)        // 4096
#define CR   (BB*MM)        // 2048
#define PADS 1152           // padded kv rows
#define PW   1152           // V^T row stride
#define QW   640            // fused QKV row width
// per-layer converted-weight region (elems) and job offsets
#define WL   4292608L
#define WOF_WQ   0L
#define WOF_WKV  262144L
#define WOF_WO   327680L
#define WOF_CWQ  589824L
#define WOF_CWKV 851968L
#define WOF_CWO  884736L
#define WOF_W1   1146880L
#define WOF_W2   3244032L

// ---------------- scratch (static device globals) --------------------------
__device__ float g_x   [RR*DD];
__device__ float g_q   [RR*DD];          // wo / ca_wq fp32 out buffer
__device__ float g_bias[HH*1024];
__device__ float g_rotc[1024*16];
__device__ float g_rots[1024*16];
__device__ __nv_bfloat16 g_AH[(size_t)RR*2048];  // partitioned act splits
__device__ __nv_bfloat16 g_AL[(size_t)RR*2048];
__device__ __nv_bfloat16 g_GH[(size_t)RR*FFI];   // GLU output split
__device__ __nv_bfloat16 g_GL[(size_t)RR*FFI];
__device__ __nv_bfloat16 g_BH[(size_t)LL*WL];    // all converted weights
__device__ __nv_bfloat16 g_BL[(size_t)LL*WL];
__device__ __nv_bfloat16 g_KH[(size_t)BB*PADS*DH];
__device__ __nv_bfloat16 g_KL[(size_t)BB*PADS*DH];
__device__ __nv_bfloat16 g_VTH[(size_t)BB*DH*PW];
__device__ __nv_bfloat16 g_VTL[(size_t)BB*DH*PW];

// ---------------- reductions ------------------------------------------------
__device__ __forceinline__ float warpSum(float v){
    #pragma unroll
    for (int o=16;o;o>>=1) v += __shfl_xor_sync(0xffffffffu, v, o);
    return v;
}
__device__ __forceinline__ float warpMax(float v){
    #pragma unroll
    for (int o=16;o;o>>=1) v = fmaxf(v, __shfl_xor_sync(0xffffffffu, v, o));
    return v;
}

// ---------------- bf16 split helpers ---------------------------------------
__device__ __forceinline__ void split_bf16(float x, unsigned short& h, unsigned short& l){
    __nv_bfloat16 hb = __float2bfloat16_rn(x);
    __nv_bfloat16 lb = __float2bfloat16_rn(x - __bfloat162float(hb));
    h = __bfloat16_as_ushort(hb);
    l = __bfloat16_as_ushort(lb);
}
__device__ __forceinline__ void splitpack(float a, float b, uint32_t& hp, uint32_t& lp){
    unsigned short h0,l0,h1,l1;
    split_bf16(a,h0,l0); split_bf16(b,h1,l1);
    hp = (uint32_t)h0 | ((uint32_t)h1 << 16);
    lp = (uint32_t)l0 | ((uint32_t)l1 << 16);
}

// ---------------- elementwise ----------------------------------------------
__global__ void copy_kernel(const float* __restrict__ in, float* __restrict__ out, int n){
    for (int i = blockIdx.x*blockDim.x + threadIdx.x; i < n; i += gridDim.x*blockDim.x)
        out[i] = in[i];
}
// rel-pos bias table
__global__ void bias_tab_kernel(const float* __restrict__ rel_emb, float* __restrict__ tab){
    int n = blockIdx.x*256 + threadIdx.x;
    if (n >= 1024) return;
    int bucket;
    if (n < 16) bucket = n;
    else {
        int large = 16 + (int)(logf((float)n * 0.0625f) * (16.0f / 2.0794415416798357f));
        bucket = large < 31 ? large : 31;
    }
    #pragma unroll
    for (int h = 0; h < HH; h++)
        tab[h*1024 + n] = rel_emb[bucket*HH + h];
}
// rotary cos/sin table: [pos][m]
__global__ void rot_tab_kernel(float* __restrict__ rc, float* __restrict__ rs){
    int idx = blockIdx.x*256 + threadIdx.x;
    if (idx >= 1024*16) return;
    int pos = idx >> 4, m = idx & 15;
    float f = (float)pos * powf(10000.f, -(float)m * (1.f/16.f));
    rc[idx] = cosf(f);
    rs[idx] = sinf(f);
}
// null kv row (j=0)
__global__ void nullkv_kernel(const float* __restrict__ null_kv,
                              __nv_bfloat16* __restrict__ KH, __nv_bfloat16* __restrict__ KL,
                              __nv_bfloat16* __restrict__ VTH, __nv_bfloat16* __restrict__ VTL){
    int b = blockIdx.x, d = threadIdx.x;
    unsigned short h, l;
    split_bf16(null_kv[d], h, l);
    KH[(long)b*PADS*DH + d] = __ushort_as_bfloat16(h);
    KL[(long)b*PADS*DH + d] = __ushort_as_bfloat16(l);
    split_bf16(null_kv[DH + d], h, l);
    VTH[((long)b*DH + d)*PW] = __ushort_as_bfloat16(h);
    VTL[((long)b*DH + d)*PW] = __ushort_as_bfloat16(l);
}

// ---------------- batched weight conversion (all layers, one launch) --------
__global__ __launch_bounds__(256) void convBT_all(
    const float* __restrict__ wq,  const float* __restrict__ wkv,
    const float* __restrict__ wo,  const float* __restrict__ cwq,
    const float* __restrict__ cwkv,const float* __restrict__ cwo,
    const float* __restrict__ w1,  const float* __restrict__ w2,
    __nv_bfloat16* __restrict__ hi, __nv_bfloat16* __restrict__ lo){
    int tb = blockIdx.x;
    int layer = tb / 4192;
    int rt = tb - layer*4192;
    const float* src; int K, N, ntx, perm = 0; long dstoff;
    if      (rt < 256 ){           src = wq  + (size_t)layer*512*512;  K=512;  N=512;  ntx=16;  dstoff=WOF_WQ;  }
    else if (rt < 320 ){ rt-=256;  src = wkv + (size_t)layer*512*128;  K=512;  N=128;  ntx=4;   dstoff=WOF_WKV; }
    else if (rt < 576 ){ rt-=320;  src = wo  + (size_t)layer*512*512;  K=512;  N=512;  ntx=16;  dstoff=WOF_WO;  }
    else if (rt < 832 ){ rt-=576;  src = cwq + (size_t)layer*512*512;  K=512;  N=512;  ntx=16;  dstoff=WOF_CWQ; }
    else if (rt < 864 ){ rt-=832;  src = cwkv+ (size_t)layer*256*128;  K=256;  N=128;  ntx=4;   dstoff=WOF_CWKV;}
    else if (rt < 1120){ rt-=864;  src = cwo + (size_t)layer*512*512;  K=512;  N=512;  ntx=16;  dstoff=WOF_CWO; }
    else if (rt < 3168){ rt-=1120; src = w1  + (size_t)layer*512*4096; K=512;  N=4096; ntx=128; dstoff=WOF_W1; perm=1; }
    else               { rt-=3168; src = w2  + (size_t)layer*2048*512; K=2048; N=512;  ntx=16;  dstoff=WOF_W2;  }
    dstoff += (long)layer * WL;
    int n0 = (rt % ntx)*32, k0 = (rt / ntx)*32;

    __shared__ float tile[32][33];
    int tx = threadIdx.x & 31, ty = threadIdx.x >> 5;
    int cc = n0 + tx;
    int scol = perm ? ((cc>>1) + (cc&1)*FFI) : cc;
    #pragma unroll
    for (int i = 0; i < 4; i++)
        tile[ty + 8*i][tx] = src[(long)(k0 + ty + 8*i)*N + scol];
    __syncthreads();
    #pragma unroll
    for (int i = 0; i < 4; i++){
        int n = ty + 8*i;
        float v = tile[tx][n];
        unsigned short h, l;
        split_bf16(v, h, l);
        long off = dstoff + (long)(n0 + n)*K + k0 + tx;
        hi[off] = __ushort_as_bfloat16(h);
        lo[off] = __ushort_as_bfloat16(l);
    }
}

// ---------------- warp-per-row layernorm family -----------------------------
__global__ __launch_bounds__(256) void ln_split_w(const float* __restrict__ in,
                                                  const float* __restrict__ g,
                                                  __nv_bfloat16* __restrict__ hi,
                                                  __nv_bfloat16* __restrict__ lo, int cols){
    int wid = threadIdx.x >> 5, lane = threadIdx.x & 31;
    long row = (long)blockIdx.x*8 + wid;
    const float* p = in + row*cols;
    int nc = cols >> 7;
    float v[16];
    float s = 0.f;
    for (int c = 0; c < nc; c++){
        float4 q = *(const float4*)(p + c*128 + lane*4);
        v[c*4+0]=q.x; v[c*4+1]=q.y; v[c*4+2]=q.z; v[c*4+3]=q.w;
        s += q.x + q.y + q.z + q.w;
    }
    float mu = warpSum(s) / (float)cols;
    float s2 = 0.f;
    for (int c = 0; c < nc*4; c++){ v[c] -= mu; s2 += v[c]*v[c]; }
    float inv = rsqrtf(warpSum(s2) / (float)cols + 1e-5f);
    for (int c = 0; c < nc; c++){
        int col = c*128 + lane*4;
        uint32_t hp0, lp0, hp1, lp1;
        splitpack(v[c*4+0]*inv*g[col],   v[c*4+1]*inv*g[col+1], hp0, lp0);
        splitpack(v[c*4+2]*inv*g[col+2], v[c*4+3]*inv*g[col+3], hp1, lp1);
        uint2 hh; hh.x = hp0; hh.y = hp1;
        uint2 ll; ll.x = lp0; ll.y = lp1;
        *(uint2*)(hi + row*cols + col) = hh;
        *(uint2*)(lo + row*cols + col) = ll;
    }
}
__global__ __launch_bounds__(256) void ln_res_split_w(const float* __restrict__ qin,
                                                      const float* __restrict__ g1,
                                                      float* __restrict__ x,
                                                      const float* __restrict__ g2,
                                                      __nv_bfloat16* __restrict__ hi,
                                                      __nv_bfloat16* __restrict__ lo){
    int wid = threadIdx.x >> 5, lane = threadIdx.x & 31;
    long row = (long)blockIdx.x*8 + wid;
    const float* p = qin + row*DD;
    float* px = x + row*DD;
    float v[16];
    float s = 0.f;
    #pragma unroll
    for (int c = 0; c < 4; c++){
        float4 q = *(const float4*)(p + c*128 + lane*4);
        v[c*4+0]=q.x; v[c*4+1]=q.y; v[c*4+2]=q.z; v[c*4+3]=q.w;
        s += q.x + q.y + q.z + q.w;
    }
    float mu = warpSum(s) * (1.f/512.f);
    float s2 = 0.f;
    #pragma unroll
    for (int c = 0; c < 16; c++){ v[c] -= mu; s2 += v[c]*v[c]; }
    float inv = rsqrtf(warpSum(s2) * (1.f/512.f) + 1e-5f);
    float s3 = 0.f;
    #pragma unroll
    for (int c = 0; c < 4; c++){
        int col = c*128 + lane*4;
        float4 xa = *(const float4*)(px + col);
        float4 ga = *(const float4*)(g1 + col);
        xa.x += v[c*4+0]*inv*ga.x; xa.y += v[c*4+1]*inv*ga.y;
        xa.z += v[c*4+2]*inv*ga.z; xa.w += v[c*4+3]*inv*ga.w;
        *(float4*)(px + col) = xa;
        v[c*4+0]=xa.x; v[c*4+1]=xa.y; v[c*4+2]=xa.z; v[c*4+3]=xa.w;
        s3 += xa.x + xa.y + xa.z + xa.w;
    }
    float mu2 = warpSum(s3) * (1.f/512.f);
    float s4 = 0.f;
    #pragma unroll
    for (int c = 0; c < 16; c++){ v[c] -= mu2; s4 += v[c]*v[c]; }
    float inv2 = rsqrtf(warpSum(s4) * (1.f/512.f) + 1e-5f);
    #pragma unroll
    for (int c = 0; c < 4; c++){
        int col = c*128 + lane*4;
        float4 ga = *(const float4*)(g2 + col);
        uint32_t hp0, lp0, hp1, lp1;
        splitpack(v[c*4+0]*inv2*ga.x, v[c*4+1]*inv2*ga.y, hp0, lp0);
        splitpack(v[c*4+2]*inv2*ga.z, v[c*4+3]*inv2*ga.w, hp1, lp1);
        uint2 hh; hh.x = hp0; hh.y = hp1;
        uint2 ll; ll.x = lp0; ll.y = lp1;
        *(uint2*)(hi + row*DD + col) = hh;
        *(uint2*)(lo + row*DD + col) = ll;
    }
}
__global__ __launch_bounds__(256) void final_ln_w(const float* __restrict__ in,
                                                  const float* __restrict__ g,
                                                  float* __restrict__ out){
    int wid = threadIdx.x >> 5, lane = threadIdx.x & 31;
    long row = (long)blockIdx.x*8 + wid;
    const float* p = in + row*DD;
    float v[16];
    float mxl = -3.4e38f;
    #pragma unroll
    for (int c = 0; c < 4; c++){
        float4 q = *(const float4*)(p + c*128 + lane*4);
        v[c*4+0]=q.x; v[c*4+1]=q.y; v[c*4+2]=q.z; v[c*4+3]=q.w;
        mxl = fmaxf(mxl, fmaxf(fmaxf(q.x,q.y), fmaxf(q.z,q.w)));
    }
    float mx = warpMax(mxl);
    float s = 0.f;
    #pragma unroll
    for (int c = 0; c < 16; c++){ v[c] /= mx; s += v[c]; }
    float mu = warpSum(s) * (1.f/512.f);
    float s2 = 0.f;
    #pragma unroll
    for (int c = 0; c < 16; c++){ v[c] -= mu; s2 += v[c]*v[c]; }
    float inv = rsqrtf(warpSum(s2) * (1.f/512.f) + 1e-5f);
    #pragma unroll
    for (int c = 0; c < 4; c++){
        int col = c*128 + lane*4;
        float4 ga = *(const float4*)(g + col);
        float4 o;
        o.x = v[c*4+0]*inv*ga.x; o.y = v[c*4+1]*inv*ga.y;
        o.z = v[c*4+2]*inv*ga.z; o.w = v[c*4+3]*inv*ga.w;
        *(float4*)(out + row*DD + col) = o;
    }
}

// ============================================================================
//  mma helpers
// ============================================================================
__device__ __forceinline__ uint32_t smem_u32(const void* p){
    uint32_t a;
    asm("{ .reg .u64 t; cvta.to.shared.u64 t, %1; cvt.u32.u64 %0, t; }" : "=r"(a) : "l"(p));
    return a;
}
__device__ __forceinline__ void cpg(uint32_t sm, const void* g){
    asm volatile("cp.async.cg.shared.global [%0], [%1], 16;" :: "r"(sm), "l"(g));
}
#define CP_COMMIT() asm volatile("cp.async.commit_group;" ::: "memory")
#define CP_WAIT0()  asm volatile("cp.async.wait_group 0;" ::: "memory")
#define CP_WAIT1()  asm volatile("cp.async.wait_group 1;" ::: "memory")
#define CP_WAIT2()  asm volatile("cp.async.wait_group 2;" ::: "memory")
#define CP_WAIT3()  asm volatile("cp.async.wait_group 3;" ::: "memory")
__device__ __forceinline__ void ldsm4(uint32_t* r, uint32_t addr){
    asm volatile("ldmatrix.sync.aligned.m8n8.x4.shared.b16 {%0,%1,%2,%3}, [%4];"
        : "=r"(r[0]),"=r"(r[1]),"=r"(r[2]),"=r"(r[3]) : "r"(addr));
}
__device__ __forceinline__ void mma16816(float* d, const uint32_t* a, uint32_t b0, uint32_t b1){
    asm volatile("mma.sync.aligned.m16n8k16.row.col.f32.bf16.bf16.f32 "
        "{%0,%1,%2,%3}, {%4,%5,%6,%7}, {%8,%9}, {%0,%1,%2,%3};"
        : "+f"(d[0]),"+f"(d[1]),"+f"(d[2]),"+f"(d[3])
        : "r"(a[0]),"r"(a[1]),"r"(a[2]),"r"(a[3]), "r"(b0),"r"(b1));
}
#define SWOFF(r,c)  ((((r)*4 + ((c) ^ (((r)>>1)&3)))) << 4)
#define SWOFF8(r,c) ((((r)*8 + ((c) ^ ((r)&7)))) << 4)

#define COMPUTE_128x128(ss)                                                        \
    _Pragma("unroll")                                                              \
    for (int s = 0; s < 2; s++){                                                   \
        uint32_t ah[4][4], al[4][4], bhf[4][2], blf[4][2];                         \
        _Pragma("unroll")                                                          \
        for (int mt = 0; mt < 4; mt++){                                            \
            int r = wm + mt*16 + (lane & 15);                                      \
            int cl = 2*s + (lane >> 4);                                            \
            uint32_t addr = (ss) + SWOFF(r, cl);                                   \
            ldsm4(ah[mt], addr);                                                   \
            ldsm4(al[mt], addr + 8192);                                            \
        }                                                                          \
        _Pragma("unroll")                                                          \
        for (int g = 0; g < 2; g++){                                               \
            int r = wn + g*16 + (lane & 7) + ((lane >> 4) << 3);                   \
            int cl = 2*s + ((lane >> 3) & 1);                                      \
            uint32_t addr = (ss) + 16384 + SWOFF(r, cl);                           \
            uint32_t tmp[4];                                                       \
            ldsm4(tmp, addr);                                                      \
            bhf[2*g][0]=tmp[0]; bhf[2*g][1]=tmp[1]; bhf[2*g+1][0]=tmp[2]; bhf[2*g+1][1]=tmp[3]; \
            ldsm4(tmp, addr + 8192);                                               \
            blf[2*g][0]=tmp[0]; blf[2*g][1]=tmp[1]; blf[2*g+1][0]=tmp[2]; blf[2*g+1][1]=tmp[3]; \
        }                                                                          \
        _Pragma("unroll")                                                          \
        for (int mt = 0; mt < 4; mt++)                                             \
            _Pragma("unroll")                                                      \
            for (int nt = 0; nt < 4; nt++){                                        \
                mma16816(acc[mt][nt], ah[mt], bhf[nt][0], bhf[nt][1]);             \
                mma16816(acc[mt][nt], ah[mt], blf[nt][0], blf[nt][1]);             \
                mma16816(acc[mt][nt], al[mt], bhf[nt][0], bhf[nt][1]);             \
            }                                                                      \
    }

#define GEMM_PREAMBLE                                                              \
    extern __shared__ __align__(16) char sm[];                                     \
    uint32_t sb = smem_u32(sm);                                                    \
    int t = threadIdx.x, lane = t & 31, warp = t >> 5;                             \
    int wm = (warp >> 2) * 64, wn = (warp & 3) * 32;                               \
    long rowBase = (long)blockIdx.y * 128;                                         \
    long colBase = (long)blockIdx.x * 128;                                         \
    const __nv_bfloat16* srcs[4] = { Ah + rowBase*K, Al + rowBase*K,               \
                                     Bh + colBase*K, Bl + colBase*K };             \
    int lr = t >> 2, lc = t & 3;                                                   \
    float acc[4][4][4];                                                            \
    _Pragma("unroll")                                                              \
    for (int i=0;i<4;i++)                                                          \
        _Pragma("unroll")                                                          \
        for (int j=0;j<4;j++)                                                      \
            _Pragma("unroll")                                                      \
            for (int e=0;e<4;e++) acc[i][j][e] = 0.f;

#define GEMM_MAINLOOP                                                              \
    int nch = K >> 5;                                                              \
    DLOAD(0, 0);                                                                   \
    for (int c = 0; c < nch; c++){                                                 \
        int st = c & 1;                                                            \
        if (c + 1 < nch){ DLOAD((c+1)&1, (c+1)*32); CP_WAIT1(); }                  \
        else CP_WAIT0();                                                           \
        __syncthreads();                                                           \
        uint32_t ss = sb + st*32768;                                               \
        COMPUTE_128x128(ss);                                                       \
        __syncthreads();                                                           \
    }

#define DLOAD(st, k0) do {                                                  \
    _Pragma("unroll")                                                       \
    for (int tt = 0; tt < 4; tt++){                                         \
        const __nv_bfloat16* s = srcs[tt] + (k0);                           \
        uint32_t so = sb + (st)*32768 + tt*8192;                            \
        cpg(so + SWOFF(lr, lc),      s + (long)lr*K + lc*8);                \
        cpg(so + SWOFF(lr+64, lc),   s + (long)(lr+64)*K + lc*8);           \
    }                                                                       \
    CP_COMMIT(); } while(0)

// ---------------- dense GEMM: C = A[MxK] @ B'[NxK]^T (+=C if addC) ----------
__global__ __launch_bounds__(256, 2) void tgemm3(const __nv_bfloat16* __restrict__ Ah,
                                                 const __nv_bfloat16* __restrict__ Al,
                                                 const __nv_bfloat16* __restrict__ Bh,
                                                 const __nv_bfloat16* __restrict__ Bl,
                                                 float* __restrict__ C,
                                                 int M, int N, int K, int addC){
    GEMM_PREAMBLE
    GEMM_MAINLOOP
    #pragma unroll
    for (int mt = 0; mt < 4; mt++){
        long r = rowBase + wm + mt*16 + (lane >> 2);
        #pragma unroll
        for (int nt = 0; nt < 4; nt++){
            long cc = colBase + wn + nt*8 + 2*(lane & 3);
            float2 v0; v0.x = acc[mt][nt][0]; v0.y = acc[mt][nt][1];
            float2 v1; v1.x = acc[mt][nt][2]; v1.y = acc[mt][nt][3];
            float2* p0 = (float2*)(C + r*N + cc);
            float2* p1 = (float2*)(C + (r+8)*N + cc);
            if (addC){
                float2 c0 = *p0, c1 = *p1;
                v0.x += c0.x; v0.y += c0.y;
                v1.x += c1.x; v1.y += c1.y;
            }
            *p0 = v0;
            *p1 = v1;
        }
    }
}

// ---------------- GLU-fused GEMM -------------------------------------------
__global__ __launch_bounds__(256, 2) void tgemm3_glu(const __nv_bfloat16* __restrict__ Ah,
                                                     const __nv_bfloat16* __restrict__ Al,
                                                     const __nv_bfloat16* __restrict__ Bh,
                                                     const __nv_bfloat16* __restrict__ Bl,
                                                     __nv_bfloat16* __restrict__ GH,
                                                     __nv_bfloat16* __restrict__ GL,
                                                     int M, int N, int K){
    GEMM_PREAMBLE
    GEMM_MAINLOOP
    #pragma unroll
    for (int mt = 0; mt < 4; mt++){
        long r = rowBase + wm + mt*16 + (lane >> 2);
        #pragma unroll
        for (int nt = 0; nt < 4; nt++){
            long oc = (colBase + wn + nt*8)/2 + (lane & 3);
            float h0 = acc[mt][nt][0], gg0 = acc[mt][nt][1];
            float h1 = acc[mt][nt][2], gg1 = acc[mt][nt][3];
            float v0 = h0 * (gg0 / (1.f + expf(-gg0)));
            float v1 = h1 * (gg1 / (1.f + expf(-gg1)));
            unsigned short hs, ls;
            split_bf16(v0, hs, ls);
            GH[r*FFI + oc] = __ushort_as_bfloat16(hs);
            GL[r*FFI + oc] = __ushort_as_bfloat16(ls);
            split_bf16(v1, hs, ls);
            GH[(r+8)*FFI + oc] = __ushort_as_bfloat16(hs);
            GL[(r+8)*FFI + oc] = __ushort_as_bfloat16(ls);
        }
    }
}

// ---------------- cross-attn Q GEMM: scale + split epilogue -----------------
__global__ __launch_bounds__(256, 2) void tgemm3_qsplit(const __nv_bfloat16* __restrict__ Ah,
                                                        const __nv_bfloat16* __restrict__ Al,
                                                        const __nv_bfloat16* __restrict__ Bh,
                                                        const __nv_bfloat16* __restrict__ Bl,
                                                        __nv_bfloat16* __restrict__ QH,
                                                        __nv_bfloat16* __restrict__ QL,
                                                        int M, int N, int K){
    GEMM_PREAMBLE
    GEMM_MAINLOOP
    const float sc = 0.125f;
    #pragma unroll
    for (int mt = 0; mt < 4; mt++){
        long r = rowBase + wm + mt*16 + (lane >> 2);
        #pragma unroll
        for (int nt = 0; nt < 4; nt++){
            long cc = colBase + wn + nt*8 + 2*(lane & 3);
            uint32_t hp, lp;
            splitpack(acc[mt][nt][0]*sc, acc[mt][nt][1]*sc, hp, lp);
            *(uint32_t*)(QH + r*N + cc) = hp;
            *(uint32_t*)(QL + r*N + cc) = lp;
            splitpack(acc[mt][nt][2]*sc, acc[mt][nt][3]*sc, hp, lp);
            *(uint32_t*)(QH + (r+8)*N + cc) = hp;
            *(uint32_t*)(QL + (r+8)*N + cc) = lp;
        }
    }
}

// ---------------- cross-attn KV GEMM: direct K/V^T split epilogue ----------
// N = 128: cols [0,64) K, [64,128) V. Row = context row: b = row>>9, j = (row&511)+1.
__global__ __launch_bounds__(256, 2) void tgemm3_kv(const __nv_bfloat16* __restrict__ Ah,
                                                    const __nv_bfloat16* __restrict__ Al,
                                                    const __nv_bfloat16* __restrict__ Bh,
                                                    const __nv_bfloat16* __restrict__ Bl,
                                                    __nv_bfloat16* __restrict__ KHp,
                                                    __nv_bfloat16* __restrict__ KLp,
                                                    __nv_bfloat16* __restrict__ VTH,
                                                    __nv_bfloat16* __restrict__ VTL,
                                                    int M, int N, int K){
    GEMM_PREAMBLE
    GEMM_MAINLOOP
    #pragma unroll
    for (int mt = 0; mt < 4; mt++){
        long row = rowBase + wm + mt*16 + (lane >> 2);
        int b = (int)(row >> 9), pos = (int)(row & 511);
        #pragma unroll
        for (int nt = 0; nt < 4; nt++){
            int cc = wn + nt*8 + 2*(lane & 3);
            if (cc < 64){
                #pragma unroll
                for (int half = 0; half < 2; half++){
                    long ko = ((long)b*PADS + pos + half*8 + 1)*DH + cc;
                    uint32_t hp, lp;
                    splitpack(acc[mt][nt][half*2+0], acc[mt][nt][half*2+1], hp, lp);
                    *(uint32_t*)(KHp + ko) = hp;
                    *(uint32_t*)(KLp + ko) = lp;
                }
            } else {
                #pragma unroll
                for (int e = 0; e < 4; e++){
                    int d = cc - 64 + (e & 1);
                    long j = pos + (e >> 1)*8 + 1;
                    unsigned short h, l;
                    split_bf16(acc[mt][nt][e], h, l);
                    VTH[((long)b*DH + d)*PW + j] = __ushort_as_bfloat16(h);
                    VTL[((long)b*DH + d)*PW + j] = __ushort_as_bfloat16(l);
                }
            }
        }
    }
}

// ---------------- self-attn QKV GEMM: rotary/scale/split epilogue -----------
__global__ __launch_bounds__(256, 2) void tgemm3_qkv(const __nv_bfloat16* __restrict__ Ah,
                                                     const __nv_bfloat16* __restrict__ Al,
                                                     const __nv_bfloat16* __restrict__ Bh,
                                                     const __nv_bfloat16* __restrict__ Bl,
                                                     __nv_bfloat16* __restrict__ QH,
                                                     __nv_bfloat16* __restrict__ QL,
                                                     __nv_bfloat16* __restrict__ KHp,
                                                     __nv_bfloat16* __restrict__ KLp,
                                                     __nv_bfloat16* __restrict__ VTH,
                                                     __nv_bfloat16* __restrict__ VTL,
                                                     const float* __restrict__ rotc,
                                                     const float* __restrict__ rots,
                                                     int M, int N, int K){
    GEMM_PREAMBLE
    GEMM_MAINLOOP
    int ccb = (int)colBase + wn;
    int rothalf = ((ccb & 32) == 0);
    #pragma unroll
    for (int mt = 0; mt < 4; mt++){
        long row = rowBase + wm + mt*16 + (lane >> 2);
        int b = (int)(row >> 10);
        int pos = (int)(row & 1023);
        if (ccb < 512){
            const float sc = 0.125f;
            if (rothalf){
                #pragma unroll
                for (int nt = 0; nt < 2; nt++){
                    int cc0 = ccb + nt*8 + 2*(lane & 3);
                    int d0  = nt*8 + 2*(lane & 3);
                    #pragma unroll
                    for (int half = 0; half < 2; half++){
                        long rr = row + half*8;
                        int pp = pos + half*8;
                        float a0 = acc[mt][nt][half*2+0]*sc, b0 = acc[mt][nt+2][half*2+0]*sc;
                        float a1 = acc[mt][nt][half*2+1]*sc, b1 = acc[mt][nt+2][half*2+1]*sc;
                        float c0 = rotc[pp*16 + d0],   s0 = rots[pp*16 + d0];
                        float c1 = rotc[pp*16 + d0+1], s1 = rots[pp*16 + d0+1];
                        uint32_t hp, lp;
                        splitpack(a0*c0 - b0*s0, a1*c1 - b1*s1, hp, lp);
                        *(uint32_t*)(QH + rr*DD + cc0) = hp;
                        *(uint32_t*)(QL + rr*DD + cc0) = lp;
                        splitpack(a0*s0 + b0*c0, a1*s1 + b1*c1, hp, lp);
                        *(uint32_t*)(QH + rr*DD + cc0 + 16) = hp;
                        *(uint32_t*)(QL + rr*DD + cc0 + 16) = lp;
                    }
                }
            } else {
                #pragma unroll
                for (int nt = 0; nt < 4; nt++){
                    int cc0 = ccb + nt*8 + 2*(lane & 3);
                    uint32_t hp, lp;
                    splitpack(acc[mt][nt][0]*sc, acc[mt][nt][1]*sc, hp, lp);
                    *(uint32_t*)(QH + row*DD + cc0) = hp;
                    *(uint32_t*)(QL + row*DD + cc0) = lp;
                    splitpack(acc[mt][nt][2]*sc, acc[mt][nt][3]*sc, hp, lp);
                    *(uint32_t*)(QH + (row+8)*DD + cc0) = hp;
                    *(uint32_t*)(QL + (row+8)*DD + cc0) = lp;
                }
            }
        } else if (ccb < 576){
            if (rothalf){
                #pragma unroll
                for (int nt = 0; nt < 2; nt++){
                    int d0 = nt*8 + 2*(lane & 3);
                    #pragma unroll
                    for (int half = 0; half < 2; half++){
                        int pp = pos + half*8;
                        long ko = ((long)b*PADS + pp + 1)*DH;
                        float a0 = acc[mt][nt][half*2+0], b0 = acc[mt][nt+2][half*2+0];
                        float a1 = acc[mt][nt][half*2+1], b1 = acc[mt][nt+2][half*2+1];
                        float c0 = rotc[pp*16 + d0],   s0 = rots[pp*16 + d0];
                        float c1 = rotc[pp*16 + d0+1], s1 = rots[pp*16 + d0+1];
                        uint32_t hp, lp;
                        splitpack(a0*c0 - b0*s0, a1*c1 - b1*s1, hp, lp);
                        *(uint32_t*)(KHp + ko + d0) = hp;
                        *(uint32_t*)(KLp + ko + d0) = lp;
                        splitpack(a0*s0 + b0*c0, a1*s1 + b1*c1, hp, lp);
                        *(uint32_t*)(KHp + ko + d0 + 16) = hp;
                        *(uint32_t*)(KLp + ko + d0 + 16) = lp;
                    }
                }
            } else {
                #pragma unroll
                for (int nt = 0; nt < 4; nt++){
                    int d0 = 32 + nt*8 + 2*(lane & 3);
                    #pragma unroll
                    for (int half = 0; half < 2; half++){
                        long ko = ((long)b*PADS + pos + half*8 + 1)*DH;
                        uint32_t hp, lp;
                        splitpack(acc[mt][nt][half*2+0], acc[mt][nt][half*2+1], hp, lp);
                        *(uint32_t*)(KHp + ko + d0) = hp;
                        *(uint32_t*)(KLp + ko + d0) = lp;
                    }
                }
            }
        } else {
            #pragma unroll
            for (int nt = 0; nt < 4; nt++){
                int d0 = (ccb - 576) + nt*8 + 2*(lane & 3);
                #pragma unroll
                for (int e = 0; e < 4; e++){
                    int d = d0 + (e & 1);
                    long j = pos + (e >> 1)*8 + 1;
                    unsigned short h, l;
                    split_bf16(acc[mt][nt][e], h, l);
                    VTH[((long)b*DH + d)*PW + j] = __ushort_as_bfloat16(h);
                    VTL[((long)b*DH + d)*PW + j] = __ushort_as_bfloat16(l);
                }
            }
        }
    }
}
#undef DLOAD

// ============================================================================
//  Fused flash attention, 2-stage pipelined K/V tiles
//  smem: Q 16K | stage0 {K 16K, V 16K} | stage1 {K 16K, V 16K} | bias 4K
// ============================================================================
#define FSM_Q   0
#define FSM_ST  16384
#define FSM_SS  32768
#define FSM_B   81920
#define FSM_TOT 86016

__global__ __launch_bounds__(128) void flash_attn(const __nv_bfloat16* __restrict__ Qh,
                                                  const __nv_bfloat16* __restrict__ Ql,
                                                  const __nv_bfloat16* __restrict__ KHp,
                                                  const __nv_bfloat16* __restrict__ KLp,
                                                  const __nv_bfloat16* __restrict__ VTHp,
                                                  const __nv_bfloat16* __restrict__ VTLp,
                                                  const float* __restrict__ bias_tab,
                                                  __nv_bfloat16* __restrict__ OH,
                                                  __nv_bfloat16* __restrict__ OL,
                                                  int nkv, int cb){
    extern __shared__ __align__(16) char sm[];
    uint32_t sb = smem_u32(sm);
    int t = threadIdx.x, lane = t & 31, warp = t >> 5;
    int bh = blockIdx.y, b = bh >> 3, h = bh & 7;
    int i0 = blockIdx.x * 64;

    const __nv_bfloat16* kh = KHp + (long)b*PADS*DH;
    const __nv_bfloat16* kl = KLp + (long)b*PADS*DH;
    const __nv_bfloat16* vh = VTHp + (long)b*DH*PW;
    const __nv_bfloat16* vl = VTLp + (long)b*DH*PW;

    #define FLOAD(st, jt) do {                                                     \
        for (int i = t; i < 512; i += 128){                                        \
            int r = i >> 3, c = i & 7;                                             \
            cpg(sb + FSM_ST + (st)*FSM_SS        + SWOFF8(r,c), kh + ((long)((jt)*64 + r))*DH + c*8); \
            cpg(sb + FSM_ST + (st)*FSM_SS + 8192 + SWOFF8(r,c), kl + ((long)((jt)*64 + r))*DH + c*8); \
        }                                                                          \
        CP_COMMIT();                                                               \
        for (int i = t; i < 512; i += 128){                                        \
            int r = i >> 3, c = i & 7;                                             \
            cpg(sb + FSM_ST + (st)*FSM_SS + 16384        + SWOFF8(r,c), vh + (long)r*PW + (jt)*64 + c*8); \
            cpg(sb + FSM_ST + (st)*FSM_SS + 16384 + 8192 + SWOFF8(r,c), vl + (long)r*PW + (jt)*64 + c*8); \
        }                                                                          \
        CP_COMMIT(); } while(0)

    // Q load (group 0) then tile-0 K/V (groups 1,2)
    {
        const __nv_bfloat16* qh = Qh + ((long)(b*NQ + i0))*DD + h*DH;
        const __nv_bfloat16* ql = Ql + ((long)(b*NQ + i0))*DD + h*DH;
        for (int i = t; i < 512; i += 128){
            int r = i >> 3, c = i & 7;
            cpg(sb + FSM_Q        + SWOFF8(r,c), qh + (long)r*DD + c*8);
            cpg(sb + FSM_Q + 8192 + SWOFF8(r,c), ql + (long)r*DD + c*8);
        }
        CP_COMMIT();
    }
    if (cb){
        float* bsm = (float*)(sm + FSM_B);
        for (int i = t; i < 1024; i += 128) bsm[i] = bias_tab[h*1024 + i];
    }
    FLOAD(0, 0);
    CP_WAIT2();       // Q ready; tile0 K/V in flight
    __syncthreads();

    uint32_t qfh[4][4], qfl[4][4];
    #pragma unroll
    for (int s = 0; s < 4; s++){
        int r = warp*16 + (lane & 15);
        int cl = 2*s + (lane >> 4);
        ldsm4(qfh[s], sb + FSM_Q + SWOFF8(r, cl));
        ldsm4(qfl[s], sb + FSM_Q + 8192 + SWOFF8(r, cl));
    }

    float o[8][4];
    #pragma unroll
    for (int i=0;i<8;i++)
        #pragma unroll
        for (int e=0;e<4;e++) o[i][e] = 0.f;
    float mx0 = -3.0e38f, mx1 = -3.0e38f, sum0 = 0.f, sum1 = 0.f;

    int jt_max = (nkv - 1) >> 6;
    if (cb){ int jm = (i0 + 64) >> 6; if (jm < jt_max) jt_max = jm; }
    const float* bsm = (const float*)(sm + FSM_B);

    for (int jt = 0; jt <= jt_max; jt++){
        int st = jt & 1;
        int hasnext = (jt < jt_max);
        if (hasnext) FLOAD(st ^ 1, jt + 1);
        if (hasnext) CP_WAIT3(); else CP_WAIT1();   // K(cur) ready
        __syncthreads();
        uint32_t ks = sb + FSM_ST + st*FSM_SS;

        float sacc[8][4];
        #pragma unroll
        for (int i=0;i<8;i++)
            #pragma unroll
            for (int e=0;e<4;e++) sacc[i][e] = 0.f;
        #pragma unroll
        for (int s = 0; s < 4; s++){
            uint32_t bhf[8][2], blf[8][2];
            #pragma unroll
            for (int g = 0; g < 4; g++){
                int r = g*16 + (lane & 7) + ((lane >> 4) << 3);
                int cl = 2*s + ((lane >> 3) & 1);
                uint32_t tmp[4];
                ldsm4(tmp, ks + SWOFF8(r, cl));
                bhf[2*g][0]=tmp[0]; bhf[2*g][1]=tmp[1]; bhf[2*g+1][0]=tmp[2]; bhf[2*g+1][1]=tmp[3];
                ldsm4(tmp, ks + 8192 + SWOFF8(r, cl));
                blf[2*g][0]=tmp[0]; blf[2*g][1]=tmp[1]; blf[2*g+1][0]=tmp[2]; blf[2*g+1][1]=tmp[3];
            }
            #pragma unroll
            for (int nt = 0; nt < 8; nt++){
                mma16816(sacc[nt], qfh[s], bhf[nt][0], bhf[nt][1]);
                mma16816(sacc[nt], qfh[s], blf[nt][0], blf[nt][1]);
                mma16816(sacc[nt], qfl[s], bhf[nt][0], bhf[nt][1]);
            }
        }

        int ibase = i0 + warp*16 + (lane >> 2);
        int jbase = jt*64 + 2*(lane & 3);
        float tmx0 = -3.0e38f, tmx1 = -3.0e38f;
        #pragma unroll
        for (int nt = 0; nt < 8; nt++){
            #pragma unroll
            for (int e = 0; e < 4; e++){
                int i = ibase + ((e >> 1) << 3);
                int j = jbase + nt*8 + (e & 1);
                float s = sacc[nt][e];
                if (cb){
                    int nn = i - j; if (nn < 0) nn = 0;
                    s += bsm[nn];
                    if (j > i + 1) s = -1e30f;
                }
                if (j >= nkv) s = -1e30f;
                sacc[nt][e] = s;
                if (e < 2) tmx0 = fmaxf(tmx0, s); else tmx1 = fmaxf(tmx1, s);
            }
        }
        tmx0 = fmaxf(tmx0, __shfl_xor_sync(0xffffffffu, tmx0, 1));
        tmx0 = fmaxf(tmx0, __shfl_xor_sync(0xffffffffu, tmx0, 2));
        tmx1 = fmaxf(tmx1, __shfl_xor_sync(0xffffffffu, tmx1, 1));
        tmx1 = fmaxf(tmx1, __shfl_xor_sync(0xffffffffu, tmx1, 2));
        float nmx0 = fmaxf(mx0, tmx0), nmx1 = fmaxf(mx1, tmx1);
        float al0 = expf(mx0 - nmx0), al1 = expf(mx1 - nmx1);
        mx0 = nmx0; mx1 = nmx1;
        sum0 *= al0; sum1 *= al1;
        #pragma unroll
        for (int nt = 0; nt < 8; nt++){
            o[nt][0] *= al0; o[nt][1] *= al0;
            o[nt][2] *= al1; o[nt][3] *= al1;
        }

        if (hasnext) CP_WAIT2(); else CP_WAIT0();   // V(cur) ready
        __syncthreads();

        float ts0 = 0.f, ts1 = 0.f;
        #pragma unroll
        for (int kg = 0; kg < 4; kg++){
            uint32_t phf[4], plf[4];
            #pragma unroll
            for (int half = 0; half < 2; half++){
                int nt = 2*kg + half;
                unsigned short hb[4], lb[4];
                #pragma unroll
                for (int e = 0; e < 4; e++){
                    float pe = expf(sacc[nt][e] - ((e < 2) ? mx0 : mx1));
                    if (e < 2) ts0 += pe; else ts1 += pe;
                    split_bf16(pe, hb[e], lb[e]);
                }
                phf[2*half+0] = (uint32_t)hb[0] | ((uint32_t)hb[1] << 16);
                phf[2*half+1] = (uint32_t)hb[2] | ((uint32_t)hb[3] << 16);
                plf[2*half+0] = (uint32_t)lb[0] | ((uint32_t)lb[1] << 16);
                plf[2*half+1] = (uint32_t)lb[2] | ((uint32_t)lb[3] << 16);
            }
            uint32_t vhf[8][2], vlf[8][2];
            #pragma unroll
            for (int g = 0; g < 4; g++){
                int r = g*16 + (lane & 7) + ((lane >> 4) << 3);
                int cl = 2*kg + ((lane >> 3) & 1);
                uint32_t tmp[4];
                ldsm4(tmp, ks + 16384 + SWOFF8(r, cl));
                vhf[2*g][0]=tmp[0]; vhf[2*g][1]=tmp[1]; vhf[2*g+1][0]=tmp[2]; vhf[2*g+1][1]=tmp[3];
                ldsm4(tmp, ks + 16384 + 8192 + SWOFF8(r, cl));
                vlf[2*g][0]=tmp[0]; vlf[2*g][1]=tmp[1]; vlf[2*g+1][0]=tmp[2]; vlf[2*g+1][1]=tmp[3];
            }
            #pragma unroll
            for (int nt = 0; nt < 8; nt++){
                mma16816(o[nt], phf, vhf[nt][0], vhf[nt][1]);
                mma16816(o[nt], phf, vlf[nt][0], vlf[nt][1]);
                mma16816(o[nt], plf, vhf[nt][0], vhf[nt][1]);
            }
        }
        ts0 += __shfl_xor_sync(0xffffffffu, ts0, 1);
        ts0 += __shfl_xor_sync(0xffffffffu, ts0, 2);
        ts1 += __shfl_xor_sync(0xffffffffu, ts1, 1);
        ts1 += __shfl_xor_sync(0xffffffffu, ts1, 2);
        sum0 += ts0; sum1 += ts1;
        __syncthreads();   // protect stage st before its reuse (loads at jt+1)
    }
    #undef FLOAD

    float inv0 = 1.f / sum0, inv1 = 1.f / sum1;
    long r0 = (long)b*NQ + i0 + warp*16 + (lane >> 2);
    #pragma unroll
    for (int nt = 0; nt < 8; nt++){
        int c = nt*8 + 2*(lane & 3);
        uint32_t hp, lp;
        splitpack(o[nt][0]*inv0, o[nt][1]*inv0, hp, lp);
        *(uint32_t*)(OH + r0*DD + h*DH + c) = hp;
        *(uint32_t*)(OL + r0*DD + h*DH + c) = lp;
        splitpack(o[nt][2]*inv1, o[nt][3]*inv1, hp, lp);
        *(uint32_t*)(OH + (r0+8)*DD + h*DH + c) = hp;
        *(uint32_t*)(OL + (r0+8)*DD + h*DH + c) = lp;
    }
}

// ---------------- orchestration --------------------------------------------
extern "C" void kernel_launch(void* const* d_in, const int* in_sizes, int n_in,
                              void* d_out, int out_size){
    const float* x_in    = (const float*)d_in[0];
    const float* ctx     = (const float*)d_in[1];
    const float* rel_emb = (const float*)d_in[2];
    const float* sa_ng   = (const float*)d_in[3];
    const float* sa_wq   = (const float*)d_in[4];
    const float* sa_wkv  = (const float*)d_in[5];
    const float* sa_null = (const float*)d_in[6];
    const float* sa_wo   = (const float*)d_in[7];
    const float* sa_og   = (const float*)d_in[8];
    const float* ca_ng   = (const float*)d_in[9];
    const float* ca_cg   = (const float*)d_in[10];
    const float* ca_wq   = (const float*)d_in[11];
    const float* ca_wkv  = (const float*)d_in[12];
    const float* ca_null = (const float*)d_in[13];
    const float* ca_wo   = (const float*)d_in[14];
    const float* ca_og   = (const float*)d_in[15];
    const float* ff_ng   = (const float*)d_in[16];
    const float* ff_w1   = (const float*)d_in[17];
    const float* ff_w2   = (const float*)d_in[18];
    const float* normg   = (const float*)d_in[19];
    float* out = (float*)d_out;

    cudaFuncSetAttribute(tgemm3,        cudaFuncAttributeMaxDynamicSharedMemorySize, 65536);
    cudaFuncSetAttribute(tgemm3_glu,    cudaFuncAttributeMaxDynamicSharedMemorySize, 65536);
    cudaFuncSetAttribute(tgemm3_qsplit, cudaFuncAttributeMaxDynamicSharedMemorySize, 65536);
    cudaFuncSetAttribute(tgemm3_kv,     cudaFuncAttributeMaxDynamicSharedMemorySize, 65536);
    cudaFuncSetAttribute(tgemm3_qkv,    cudaFuncAttributeMaxDynamicSharedMemorySize, 65536);
    cudaFuncSetAttribute(flash_attn,    cudaFuncAttributeMaxDynamicSharedMemorySize, FSM_TOT);

    float *X,*QO,*BT,*RC,*RS;
    __nv_bfloat16 *AH,*AL,*GH,*GL,*BH,*BL,*KH,*KL,*VTH,*VTL;
    cudaGetSymbolAddress((void**)&X,    g_x);
    cudaGetSymbolAddress((void**)&QO,   g_q);
    cudaGetSymbolAddress((void**)&BT,   g_bias);
    cudaGetSymbolAddress((void**)&RC,   g_rotc);
    cudaGetSymbolAddress((void**)&RS,   g_rots);
    cudaGetSymbolAddress((void**)&AH,   g_AH);
    cudaGetSymbolAddress((void**)&AL,   g_AL);
    cudaGetSymbolAddress((void**)&GH,   g_GH);
    cudaGetSymbolAddress((void**)&GL,   g_GL);
    cudaGetSymbolAddress((void**)&BH,   g_BH);
    cudaGetSymbolAddress((void**)&BL,   g_BL);
    cudaGetSymbolAddress((void**)&KH,   g_KH);
    cudaGetSymbolAddress((void**)&KL,   g_KL);
    cudaGetSymbolAddress((void**)&VTH,  g_VTH);
    cudaGetSymbolAddress((void**)&VTL,  g_VTL);
    // activation split regions inside g_AH/g_AL (8M elems each):
    __nv_bfloat16 *XQH = AH,                         *XQL = AL;                        // [0,2M)  LN(x) split
    __nv_bfloat16 *ATH = AH + (size_t)2*1024*1024,   *ATL = AL + (size_t)2*1024*1024;  // [2M,4M) ATT split
    __nv_bfloat16 *CXH = AH + (size_t)4*1024*1024,   *CXL = AL + (size_t)4*1024*1024;  // [4M,5M) ctx split
    __nv_bfloat16 *QSH = AH + (size_t)5*1024*1024,   *QSL = AL + (size_t)5*1024*1024;  // [5M,7M) Q split

    copy_kernel<<<512, 256>>>(x_in, X, RR*DD);
    bias_tab_kernel<<<4, 256>>>(rel_emb, BT);
    rot_tab_kernel<<<64, 256>>>(RC, RS);
    convBT_all<<<LL*4192, 256>>>(sa_wq, sa_wkv, sa_wo, ca_wq, ca_wkv, ca_wo,
                                 ff_w1, ff_w2, BH, BL);

    for (int l = 0; l < LL; l++){
        const __nv_bfloat16 *WBH = BH + (size_t)l*WL, *WBL = BL + (size_t)l*WL;

        // ---------------- self-attention (fully fused QKV prep) -----------
        ln_split_w<<<RR/8, 256>>>(X, sa_ng + l*DD, XQH, XQL, DD);
        nullkv_kernel<<<BB, 64>>>(sa_null + l*128, KH, KL, VTH, VTL);
        tgemm3_qkv<<<dim3(QW/128, RR/128), 256, 65536>>>(XQH, XQL, WBH + WOF_WQ, WBL + WOF_WQ,
                                                         QSH, QSL, KH, KL, VTH, VTL, RC, RS, RR, QW, DD);
        flash_attn<<<dim3(NQ/64, BB*HH), 128, FSM_TOT>>>(QSH, QSL, KH, KL, VTH, VTL, BT, ATH, ATL, NQ+1, 1);
        tgemm3<<<dim3(DD/128, RR/128), 256, 65536>>>(ATH, ATL, WBH + WOF_WO, WBL + WOF_WO, QO, RR, DD, DD, 0);
        ln_res_split_w<<<RR/8, 256>>>(QO, sa_og + l*DD, X, ca_ng + l*DD, XQH, XQL);

        // ---------------- cross-attention ----------------
        ln_split_w<<<CR/8, 256>>>(ctx, ca_cg + l*PP, CXH, CXL, PP);
        nullkv_kernel<<<BB, 64>>>(ca_null + l*128, KH, KL, VTH, VTL);
        tgemm3_kv<<<dim3(1, CR/128), 256, 65536>>>(CXH, CXL, WBH + WOF_CWKV, WBL + WOF_CWKV,
                                                   KH, KL, VTH, VTL, CR, 128, PP);
        tgemm3_qsplit<<<dim3(DD/128, RR/128), 256, 65536>>>(XQH, XQL, WBH + WOF_CWQ, WBL + WOF_CWQ,
                                                            QSH, QSL, RR, DD, DD);
        flash_attn<<<dim3(NQ/64, BB*HH), 128, FSM_TOT>>>(QSH, QSL, KH, KL, VTH, VTL, BT, ATH, ATL, MM+1, 0);
        tgemm3<<<dim3(DD/128, RR/128), 256, 65536>>>(ATH, ATL, WBH + WOF_CWO, WBL + WOF_CWO, QO, RR, DD, DD, 0);
        ln_res_split_w<<<RR/8, 256>>>(QO, ca_og + l*DD, X, ff_ng + l*DD, XQH, XQL);

        // ---------------- feed-forward (GLU fused into w1 GEMM) ------------
        tgemm3_glu<<<dim3((2*FFI)/128, RR/128), 256, 65536>>>(XQH, XQL, WBH + WOF_W1, WBL + WOF_W1,
                                                              GH, GL, RR, 2*FFI, DD);
        tgemm3<<<dim3(DD/128, RR/128), 256, 65536>>>(GH, GL, WBH + WOF_W2, WBL + WOF_W2, X, RR, DD, FFI, 1);
    }

    final_ln_w<<<RR/8, 256>>>(X, normg, out);
}

// round 14
// speedup vs baseline: 1.0059x; 1.0059x over previous
#include <cuda_runtime.h>
#include <cuda_bf16.h>
#include <math.h>
#include <stdint.h>

// Problem constants
#define BB   4
#define NQ   1024
#define MM   512
#define DD   512
#define PP   256
#define HH   8
#define DH   64
#define LL   6
#define FFI  2048
#define RR   (BB*NQ)        // 4096
#define CR   (BB*MM)        // 2048
#define PADS 1152           // padded kv rows
#define PW   1152           // V^T row stride
#define QW   640            // fused QKV row width
// per-layer converted-weight region (elems) and job offsets
#define WL   4292608L
#define WOF_WQ   0L
#define WOF_WKV  262144L
#define WOF_WO   327680L
#define WOF_CWQ  589824L
#define WOF_CWKV 851968L
#define WOF_CWO  884736L
#define WOF_W1   1146880L
#define WOF_W2   3244032L

// ---------------- scratch (static device globals) --------------------------
__device__ float g_x   [RR*DD];
__device__ float g_q   [RR*DD];
__device__ float g_bias[HH*1024];
__device__ float g_rotc[1024*16];
__device__ float g_rots[1024*16];
__device__ __nv_bfloat16 g_AH[(size_t)RR*2048];
__device__ __nv_bfloat16 g_AL[(size_t)RR*2048];
__device__ __nv_bfloat16 g_GH[(size_t)RR*FFI];
__device__ __nv_bfloat16 g_GL[(size_t)RR*FFI];
__device__ __nv_bfloat16 g_BH[(size_t)LL*WL];
__device__ __nv_bfloat16 g_BL[(size_t)LL*WL];
__device__ __nv_bfloat16 g_KH[(size_t)BB*PADS*DH];
__device__ __nv_bfloat16 g_KL[(size_t)BB*PADS*DH];
__device__ __nv_bfloat16 g_VTH[(size_t)BB*DH*PW];
__device__ __nv_bfloat16 g_VTL[(size_t)BB*DH*PW];

// ---------------- reductions ------------------------------------------------
__device__ __forceinline__ float warpSum(float v){
    #pragma unroll
    for (int o=16;o;o>>=1) v += __shfl_xor_sync(0xffffffffu, v, o);
    return v;
}
__device__ __forceinline__ float warpMax(float v){
    #pragma unroll
    for (int o=16;o;o>>=1) v = fmaxf(v, __shfl_xor_sync(0xffffffffu, v, o));
    return v;
}

// ---------------- bf16 split helpers ---------------------------------------
__device__ __forceinline__ void split_bf16(float x, unsigned short& h, unsigned short& l){
    __nv_bfloat16 hb = __float2bfloat16_rn(x);
    __nv_bfloat16 lb = __float2bfloat16_rn(x - __bfloat162float(hb));
    h = __bfloat16_as_ushort(hb);
    l = __bfloat16_as_ushort(lb);
}
__device__ __forceinline__ void splitpack(float a, float b, uint32_t& hp, uint32_t& lp){
    unsigned short h0,l0,h1,l1;
    split_bf16(a,h0,l0); split_bf16(b,h1,l1);
    hp = (uint32_t)h0 | ((uint32_t)h1 << 16);
    lp = (uint32_t)l0 | ((uint32_t)l1 << 16);
}

// ---------------- elementwise ----------------------------------------------
__global__ void copy_kernel(const float* __restrict__ in, float* __restrict__ out, int n){
    for (int i = blockIdx.x*blockDim.x + threadIdx.x; i < n; i += gridDim.x*blockDim.x)
        out[i] = in[i];
}
__global__ void bias_tab_kernel(const float* __restrict__ rel_emb, float* __restrict__ tab){
    int n = blockIdx.x*256 + threadIdx.x;
    if (n >= 1024) return;
    int bucket;
    if (n < 16) bucket = n;
    else {
        int large = 16 + (int)(logf((float)n * 0.0625f) * (16.0f / 2.0794415416798357f));
        bucket = large < 31 ? large : 31;
    }
    #pragma unroll
    for (int h = 0; h < HH; h++)
        tab[h*1024 + n] = rel_emb[bucket*HH + h];
}
__global__ void rot_tab_kernel(float* __restrict__ rc, float* __restrict__ rs){
    int idx = blockIdx.x*256 + threadIdx.x;
    if (idx >= 1024*16) return;
    int pos = idx >> 4, m = idx & 15;
    float f = (float)pos * powf(10000.f, -(float)m * (1.f/16.f));
    rc[idx] = cosf(f);
    rs[idx] = sinf(f);
}
__global__ void nullkv_kernel(const float* __restrict__ null_kv,
                              __nv_bfloat16* __restrict__ KH, __nv_bfloat16* __restrict__ KL,
                              __nv_bfloat16* __restrict__ VTH, __nv_bfloat16* __restrict__ VTL){
    int b = blockIdx.x, d = threadIdx.x;
    unsigned short h, l;
    split_bf16(null_kv[d], h, l);
    KH[(long)b*PADS*DH + d] = __ushort_as_bfloat16(h);
    KL[(long)b*PADS*DH + d] = __ushort_as_bfloat16(l);
    split_bf16(null_kv[DH + d], h, l);
    VTH[((long)b*DH + d)*PW] = __ushort_as_bfloat16(h);
    VTL[((long)b*DH + d)*PW] = __ushort_as_bfloat16(l);
}

// ---------------- batched weight conversion (all layers, one launch) --------
__global__ __launch_bounds__(256) void convBT_all(
    const float* __restrict__ wq,  const float* __restrict__ wkv,
    const float* __restrict__ wo,  const float* __restrict__ cwq,
    const float* __restrict__ cwkv,const float* __restrict__ cwo,
    const float* __restrict__ w1,  const float* __restrict__ w2,
    __nv_bfloat16* __restrict__ hi, __nv_bfloat16* __restrict__ lo){
    int tb = blockIdx.x;
    int layer = tb / 4192;
    int rt = tb - layer*4192;
    const float* src; int K, N, ntx, perm = 0; long dstoff;
    if      (rt < 256 ){           src = wq  + (size_t)layer*512*512;  K=512;  N=512;  ntx=16;  dstoff=WOF_WQ;  }
    else if (rt < 320 ){ rt-=256;  src = wkv + (size_t)layer*512*128;  K=512;  N=128;  ntx=4;   dstoff=WOF_WKV; }
    else if (rt < 576 ){ rt-=320;  src = wo  + (size_t)layer*512*512;  K=512;  N=512;  ntx=16;  dstoff=WOF_WO;  }
    else if (rt < 832 ){ rt-=576;  src = cwq + (size_t)layer*512*512;  K=512;  N=512;  ntx=16;  dstoff=WOF_CWQ; }
    else if (rt < 864 ){ rt-=832;  src = cwkv+ (size_t)layer*256*128;  K=256;  N=128;  ntx=4;   dstoff=WOF_CWKV;}
    else if (rt < 1120){ rt-=864;  src = cwo + (size_t)layer*512*512;  K=512;  N=512;  ntx=16;  dstoff=WOF_CWO; }
    else if (rt < 3168){ rt-=1120; src = w1  + (size_t)layer*512*4096; K=512;  N=4096; ntx=128; dstoff=WOF_W1; perm=1; }
    else               { rt-=3168; src = w2  + (size_t)layer*2048*512; K=2048; N=512;  ntx=16;  dstoff=WOF_W2;  }
    dstoff += (long)layer * WL;
    int n0 = (rt % ntx)*32, k0 = (rt / ntx)*32;

    __shared__ float tile[32][33];
    int tx = threadIdx.x & 31, ty = threadIdx.x >> 5;
    int cc = n0 + tx;
    int scol = perm ? ((cc>>1) + (cc&1)*FFI) : cc;
    #pragma unroll
    for (int i = 0; i < 4; i++)
        tile[ty + 8*i][tx] = src[(long)(k0 + ty + 8*i)*N + scol];
    __syncthreads();
    #pragma unroll
    for (int i = 0; i < 4; i++){
        int n = ty + 8*i;
        float v = tile[tx][n];
        unsigned short h, l;
        split_bf16(v, h, l);
        long off = dstoff + (long)(n0 + n)*K + k0 + tx;
        hi[off] = __ushort_as_bfloat16(h);
        lo[off] = __ushort_as_bfloat16(l);
    }
}

// ---------------- warp-per-row layernorm family -----------------------------
__global__ __launch_bounds__(256) void ln_split_w(const float* __restrict__ in,
                                                  const float* __restrict__ g,
                                                  __nv_bfloat16* __restrict__ hi,
                                                  __nv_bfloat16* __restrict__ lo, int cols){
    int wid = threadIdx.x >> 5, lane = threadIdx.x & 31;
    long row = (long)blockIdx.x*8 + wid;
    const float* p = in + row*cols;
    int nc = cols >> 7;
    float v[16];
    float s = 0.f;
    for (int c = 0; c < nc; c++){
        float4 q = *(const float4*)(p + c*128 + lane*4);
        v[c*4+0]=q.x; v[c*4+1]=q.y; v[c*4+2]=q.z; v[c*4+3]=q.w;
        s += q.x + q.y + q.z + q.w;
    }
    float mu = warpSum(s) / (float)cols;
    float s2 = 0.f;
    for (int c = 0; c < nc*4; c++){ v[c] -= mu; s2 += v[c]*v[c]; }
    float inv = rsqrtf(warpSum(s2) / (float)cols + 1e-5f);
    for (int c = 0; c < nc; c++){
        int col = c*128 + lane*4;
        uint32_t hp0, lp0, hp1, lp1;
        splitpack(v[c*4+0]*inv*g[col],   v[c*4+1]*inv*g[col+1], hp0, lp0);
        splitpack(v[c*4+2]*inv*g[col+2], v[c*4+3]*inv*g[col+3], hp1, lp1);
        uint2 hh; hh.x = hp0; hh.y = hp1;
        uint2 ll; ll.x = lp0; ll.y = lp1;
        *(uint2*)(hi + row*cols + col) = hh;
        *(uint2*)(lo + row*cols + col) = ll;
    }
}
__global__ __launch_bounds__(256) void ln_res_split_w(const float* __restrict__ qin,
                                                      const float* __restrict__ g1,
                                                      float* __restrict__ x,
                                                      const float* __restrict__ g2,
                                                      __nv_bfloat16* __restrict__ hi,
                                                      __nv_bfloat16* __restrict__ lo){
    int wid = threadIdx.x >> 5, lane = threadIdx.x & 31;
    long row = (long)blockIdx.x*8 + wid;
    const float* p = qin + row*DD;
    float* px = x + row*DD;
    float v[16];
    float s = 0.f;
    #pragma unroll
    for (int c = 0; c < 4; c++){
        float4 q = *(const float4*)(p + c*128 + lane*4);
        v[c*4+0]=q.x; v[c*4+1]=q.y; v[c*4+2]=q.z; v[c*4+3]=q.w;
        s += q.x + q.y + q.z + q.w;
    }
    float mu = warpSum(s) * (1.f/512.f);
    float s2 = 0.f;
    #pragma unroll
    for (int c = 0; c < 16; c++){ v[c] -= mu; s2 += v[c]*v[c]; }
    float inv = rsqrtf(warpSum(s2) * (1.f/512.f) + 1e-5f);
    float s3 = 0.f;
    #pragma unroll
    for (int c = 0; c < 4; c++){
        int col = c*128 + lane*4;
        float4 xa = *(const float4*)(px + col);
        float4 ga = *(const float4*)(g1 + col);
        xa.x += v[c*4+0]*inv*ga.x; xa.y += v[c*4+1]*inv*ga.y;
        xa.z += v[c*4+2]*inv*ga.z; xa.w += v[c*4+3]*inv*ga.w;
        *(float4*)(px + col) = xa;
        v[c*4+0]=xa.x; v[c*4+1]=xa.y; v[c*4+2]=xa.z; v[c*4+3]=xa.w;
        s3 += xa.x + xa.y + xa.z + xa.w;
    }
    float mu2 = warpSum(s3) * (1.f/512.f);
    float s4 = 0.f;
    #pragma unroll
    for (int c = 0; c < 16; c++){ v[c] -= mu2; s4 += v[c]*v[c]; }
    float inv2 = rsqrtf(warpSum(s4) * (1.f/512.f) + 1e-5f);
    #pragma unroll
    for (int c = 0; c < 4; c++){
        int col = c*128 + lane*4;
        float4 ga = *(const float4*)(g2 + col);
        uint32_t hp0, lp0, hp1, lp1;
        splitpack(v[c*4+0]*inv2*ga.x, v[c*4+1]*inv2*ga.y, hp0, lp0);
        splitpack(v[c*4+2]*inv2*ga.z, v[c*4+3]*inv2*ga.w, hp1, lp1);
        uint2 hh; hh.x = hp0; hh.y = hp1;
        uint2 ll; ll.x = lp0; ll.y = lp1;
        *(uint2*)(hi + row*DD + col) = hh;
        *(uint2*)(lo + row*DD + col) = ll;
    }
}
__global__ __launch_bounds__(256) void final_ln_w(const float* __restrict__ in,
                                                  const float* __restrict__ g,
                                                  float* __restrict__ out){
    int wid = threadIdx.x >> 5, lane = threadIdx.x & 31;
    long row = (long)blockIdx.x*8 + wid;
    const float* p = in + row*DD;
    float v[16];
    float mxl = -3.4e38f;
    #pragma unroll
    for (int c = 0; c < 4; c++){
        float4 q = *(const float4*)(p + c*128 + lane*4);
        v[c*4+0]=q.x; v[c*4+1]=q.y; v[c*4+2]=q.z; v[c*4+3]=q.w;
        mxl = fmaxf(mxl, fmaxf(fmaxf(q.x,q.y), fmaxf(q.z,q.w)));
    }
    float mx = warpMax(mxl);
    float s = 0.f;
    #pragma unroll
    for (int c = 0; c < 16; c++){ v[c] /= mx; s += v[c]; }
    float mu = warpSum(s) * (1.f/512.f);
    float s2 = 0.f;
    #pragma unroll
    for (int c = 0; c < 16; c++){ v[c] -= mu; s2 += v[c]*v[c]; }
    float inv = rsqrtf(warpSum(s2) * (1.f/512.f) + 1e-5f);
    #pragma unroll
    for (int c = 0; c < 4; c++){
        int col = c*128 + lane*4;
        float4 ga = *(const float4*)(g + col);
        float4 o;
        o.x = v[c*4+0]*inv*ga.x; o.y = v[c*4+1]*inv*ga.y;
        o.z = v[c*4+2]*inv*ga.z; o.w = v[c*4+3]*inv*ga.w;
        *(float4*)(out + row*DD + col) = o;
    }
}

// ============================================================================
//  mma helpers
// ============================================================================
__device__ __forceinline__ uint32_t smem_u32(const void* p){
    uint32_t a;
    asm("{ .reg .u64 t; cvta.to.shared.u64 t, %1; cvt.u32.u64 %0, t; }" : "=r"(a) : "l"(p));
    return a;
}
__device__ __forceinline__ void cpg(uint32_t sm, const void* g){
    asm volatile("cp.async.cg.shared.global [%0], [%1], 16;" :: "r"(sm), "l"(g));
}
#define CP_COMMIT() asm volatile("cp.async.commit_group;" ::: "memory")
#define CP_WAIT0()  asm volatile("cp.async.wait_group 0;" ::: "memory")
#define CP_WAIT1()  asm volatile("cp.async.wait_group 1;" ::: "memory")
__device__ __forceinline__ void ldsm4(uint32_t* r, uint32_t addr){
    asm volatile("ldmatrix.sync.aligned.m8n8.x4.shared.b16 {%0,%1,%2,%3}, [%4];"
        : "=r"(r[0]),"=r"(r[1]),"=r"(r[2]),"=r"(r[3]) : "r"(addr));
}
__device__ __forceinline__ void mma16816(float* d, const uint32_t* a, uint32_t b0, uint32_t b1){
    asm volatile("mma.sync.aligned.m16n8k16.row.col.f32.bf16.bf16.f32 "
        "{%0,%1,%2,%3}, {%4,%5,%6,%7}, {%8,%9}, {%0,%1,%2,%3};"
        : "+f"(d[0]),"+f"(d[1]),"+f"(d[2]),"+f"(d[3])
        : "r"(a[0]),"r"(a[1]),"r"(a[2]),"r"(a[3]), "r"(b0),"r"(b1));
}
#define SWOFF(r,c)  ((((r)*4 + ((c) ^ (((r)>>1)&3)))) << 4)
#define SWOFF8(r,c) ((((r)*8 + ((c) ^ ((r)&7)))) << 4)

#define COMPUTE_128x128(ss)                                                        \
    _Pragma("unroll")                                                              \
    for (int s = 0; s < 2; s++){                                                   \
        uint32_t ah[4][4], al[4][4], bhf[4][2], blf[4][2];                         \
        _Pragma("unroll")                                                          \
        for (int mt = 0; mt < 4; mt++){                                            \
            int r = wm + mt*16 + (lane & 15);                                      \
            int cl = 2*s + (lane >> 4);                                            \
            uint32_t addr = (ss) + SWOFF(r, cl);                                   \
            ldsm4(ah[mt], addr);                                                   \
            ldsm4(al[mt], addr + 8192);                                            \
        }                                                                          \
        _Pragma("unroll")                                                          \
        for (int g = 0; g < 2; g++){                                               \
            int r = wn + g*16 + (lane & 7) + ((lane >> 4) << 3);                   \
            int cl = 2*s + ((lane >> 3) & 1);                                      \
            uint32_t addr = (ss) + 16384 + SWOFF(r, cl);                           \
            uint32_t tmp[4];                                                       \
            ldsm4(tmp, addr);                                                      \
            bhf[2*g][0]=tmp[0]; bhf[2*g][1]=tmp[1]; bhf[2*g+1][0]=tmp[2]; bhf[2*g+1][1]=tmp[3]; \
            ldsm4(tmp, addr + 8192);                                               \
            blf[2*g][0]=tmp[0]; blf[2*g][1]=tmp[1]; blf[2*g+1][0]=tmp[2]; blf[2*g+1][1]=tmp[3]; \
        }                                                                          \
        _Pragma("unroll")                                                          \
        for (int mt = 0; mt < 4; mt++)                                             \
            _Pragma("unroll")                                                      \
            for (int nt = 0; nt < 4; nt++){                                        \
                mma16816(acc[mt][nt], ah[mt], bhf[nt][0], bhf[nt][1]);             \
                mma16816(acc[mt][nt], ah[mt], blf[nt][0], blf[nt][1]);             \
                mma16816(acc[mt][nt], al[mt], bhf[nt][0], bhf[nt][1]);             \
            }                                                                      \
    }

#define GEMM_PREAMBLE                                                              \
    extern __shared__ __align__(16) char sm[];                                     \
    uint32_t sb = smem_u32(sm);                                                    \
    int t = threadIdx.x, lane = t & 31, warp = t >> 5;                             \
    int wm = (warp >> 2) * 64, wn = (warp & 3) * 32;                               \
    long rowBase = (long)blockIdx.y * 128;                                         \
    long colBase = (long)blockIdx.x * 128;                                         \
    const __nv_bfloat16* srcs[4] = { Ah + rowBase*K, Al + rowBase*K,               \
                                     Bh + colBase*K, Bl + colBase*K };             \
    int lr = t >> 2, lc = t & 3;                                                   \
    float acc[4][4][4];                                                            \
    _Pragma("unroll")                                                              \
    for (int i=0;i<4;i++)                                                          \
        _Pragma("unroll")                                                          \
        for (int j=0;j<4;j++)                                                      \
            _Pragma("unroll")                                                      \
            for (int e=0;e<4;e++) acc[i][j][e] = 0.f;

#define GEMM_MAINLOOP                                                              \
    int nch = K >> 5;                                                              \
    DLOAD(0, 0);                                                                   \
    for (int c = 0; c < nch; c++){                                                 \
        int st = c & 1;                                                            \
        if (c + 1 < nch){ DLOAD((c+1)&1, (c+1)*32); CP_WAIT1(); }                  \
        else CP_WAIT0();                                                           \
        __syncthreads();                                                           \
        uint32_t ss = sb + st*32768;                                               \
        COMPUTE_128x128(ss);                                                       \
        __syncthreads();                                                           \
    }

#define DLOAD(st, k0) do {                                                  \
    _Pragma("unroll")                                                       \
    for (int tt = 0; tt < 4; tt++){                                         \
        const __nv_bfloat16* s = srcs[tt] + (k0);                           \
        uint32_t so = sb + (st)*32768 + tt*8192;                            \
        cpg(so + SWOFF(lr, lc),      s + (long)lr*K + lc*8);                \
        cpg(so + SWOFF(lr+64, lc),   s + (long)(lr+64)*K + lc*8);           \
    }                                                                       \
    CP_COMMIT(); } while(0)

// ---------------- dense GEMM ------------------------------------------------
__global__ __launch_bounds__(256, 2) void tgemm3(const __nv_bfloat16* __restrict__ Ah,
                                                 const __nv_bfloat16* __restrict__ Al,
                                                 const __nv_bfloat16* __restrict__ Bh,
                                                 const __nv_bfloat16* __restrict__ Bl,
                                                 float* __restrict__ C,
                                                 int M, int N, int K, int addC){
    GEMM_PREAMBLE
    GEMM_MAINLOOP
    #pragma unroll
    for (int mt = 0; mt < 4; mt++){
        long r = rowBase + wm + mt*16 + (lane >> 2);
        #pragma unroll
        for (int nt = 0; nt < 4; nt++){
            long cc = colBase + wn + nt*8 + 2*(lane & 3);
            float2 v0; v0.x = acc[mt][nt][0]; v0.y = acc[mt][nt][1];
            float2 v1; v1.x = acc[mt][nt][2]; v1.y = acc[mt][nt][3];
            float2* p0 = (float2*)(C + r*N + cc);
            float2* p1 = (float2*)(C + (r+8)*N + cc);
            if (addC){
                float2 c0 = *p0, c1 = *p1;
                v0.x += c0.x; v0.y += c0.y;
                v1.x += c1.x; v1.y += c1.y;
            }
            *p0 = v0;
            *p1 = v1;
        }
    }
}

// ---------------- GLU-fused GEMM -------------------------------------------
__global__ __launch_bounds__(256, 2) void tgemm3_glu(const __nv_bfloat16* __restrict__ Ah,
                                                     const __nv_bfloat16* __restrict__ Al,
                                                     const __nv_bfloat16* __restrict__ Bh,
                                                     const __nv_bfloat16* __restrict__ Bl,
                                                     __nv_bfloat16* __restrict__ GH,
                                                     __nv_bfloat16* __restrict__ GL,
                                                     int M, int N, int K){
    GEMM_PREAMBLE
    GEMM_MAINLOOP
    #pragma unroll
    for (int mt = 0; mt < 4; mt++){
        long r = rowBase + wm + mt*16 + (lane >> 2);
        #pragma unroll
        for (int nt = 0; nt < 4; nt++){
            long oc = (colBase + wn + nt*8)/2 + (lane & 3);
            float h0 = acc[mt][nt][0], gg0 = acc[mt][nt][1];
            float h1 = acc[mt][nt][2], gg1 = acc[mt][nt][3];
            float v0 = h0 * (gg0 / (1.f + expf(-gg0)));
            float v1 = h1 * (gg1 / (1.f + expf(-gg1)));
            unsigned short hs, ls;
            split_bf16(v0, hs, ls);
            GH[r*FFI + oc] = __ushort_as_bfloat16(hs);
            GL[r*FFI + oc] = __ushort_as_bfloat16(ls);
            split_bf16(v1, hs, ls);
            GH[(r+8)*FFI + oc] = __ushort_as_bfloat16(hs);
            GL[(r+8)*FFI + oc] = __ushort_as_bfloat16(ls);
        }
    }
}

// ---------------- cross-attn Q GEMM: scale + split epilogue -----------------
__global__ __launch_bounds__(256, 2) void tgemm3_qsplit(const __nv_bfloat16* __restrict__ Ah,
                                                        const __nv_bfloat16* __restrict__ Al,
                                                        const __nv_bfloat16* __restrict__ Bh,
                                                        const __nv_bfloat16* __restrict__ Bl,
                                                        __nv_bfloat16* __restrict__ QH,
                                                        __nv_bfloat16* __restrict__ QL,
                                                        int M, int N, int K){
    GEMM_PREAMBLE
    GEMM_MAINLOOP
    const float sc = 0.125f;
    #pragma unroll
    for (int mt = 0; mt < 4; mt++){
        long r = rowBase + wm + mt*16 + (lane >> 2);
        #pragma unroll
        for (int nt = 0; nt < 4; nt++){
            long cc = colBase + wn + nt*8 + 2*(lane & 3);
            uint32_t hp, lp;
            splitpack(acc[mt][nt][0]*sc, acc[mt][nt][1]*sc, hp, lp);
            *(uint32_t*)(QH + r*N + cc) = hp;
            *(uint32_t*)(QL + r*N + cc) = lp;
            splitpack(acc[mt][nt][2]*sc, acc[mt][nt][3]*sc, hp, lp);
            *(uint32_t*)(QH + (r+8)*N + cc) = hp;
            *(uint32_t*)(QL + (r+8)*N + cc) = lp;
        }
    }
}

// ---------------- cross-attn KV GEMM: direct K/V^T split epilogue ----------
__global__ __launch_bounds__(256, 2) void tgemm3_kv(const __nv_bfloat16* __restrict__ Ah,
                                                    const __nv_bfloat16* __restrict__ Al,
                                                    const __nv_bfloat16* __restrict__ Bh,
                                                    const __nv_bfloat16* __restrict__ Bl,
                                                    __nv_bfloat16* __restrict__ KHp,
                                                    __nv_bfloat16* __restrict__ KLp,
                                                    __nv_bfloat16* __restrict__ VTH,
                                                    __nv_bfloat16* __restrict__ VTL,
                                                    int M, int N, int K){
    GEMM_PREAMBLE
    GEMM_MAINLOOP
    #pragma unroll
    for (int mt = 0; mt < 4; mt++){
        long row = rowBase + wm + mt*16 + (lane >> 2);
        int b = (int)(row >> 9), pos = (int)(row & 511);
        #pragma unroll
        for (int nt = 0; nt < 4; nt++){
            int cc = wn + nt*8 + 2*(lane & 3);
            if (cc < 64){
                #pragma unroll
                for (int half = 0; half < 2; half++){
                    long ko = ((long)b*PADS + pos + half*8 + 1)*DH + cc;
                    uint32_t hp, lp;
                    splitpack(acc[mt][nt][half*2+0], acc[mt][nt][half*2+1], hp, lp);
                    *(uint32_t*)(KHp + ko) = hp;
                    *(uint32_t*)(KLp + ko) = lp;
                }
            } else {
                #pragma unroll
                for (int e = 0; e < 4; e++){
                    int d = cc - 64 + (e & 1);
                    long j = pos + (e >> 1)*8 + 1;
                    unsigned short h, l;
                    split_bf16(acc[mt][nt][e], h, l);
                    VTH[((long)b*DH + d)*PW + j] = __ushort_as_bfloat16(h);
                    VTL[((long)b*DH + d)*PW + j] = __ushort_as_bfloat16(l);
                }
            }
        }
    }
}

// ---------------- self-attn QKV GEMM: rotary/scale/split epilogue -----------
__global__ __launch_bounds__(256, 2) void tgemm3_qkv(const __nv_bfloat16* __restrict__ Ah,
                                                     const __nv_bfloat16* __restrict__ Al,
                                                     const __nv_bfloat16* __restrict__ Bh,
                                                     const __nv_bfloat16* __restrict__ Bl,
                                                     __nv_bfloat16* __restrict__ QH,
                                                     __nv_bfloat16* __restrict__ QL,
                                                     __nv_bfloat16* __restrict__ KHp,
                                                     __nv_bfloat16* __restrict__ KLp,
                                                     __nv_bfloat16* __restrict__ VTH,
                                                     __nv_bfloat16* __restrict__ VTL,
                                                     const float* __restrict__ rotc,
                                                     const float* __restrict__ rots,
                                                     int M, int N, int K){
    GEMM_PREAMBLE
    GEMM_MAINLOOP
    int ccb = (int)colBase + wn;
    int rothalf = ((ccb & 32) == 0);
    #pragma unroll
    for (int mt = 0; mt < 4; mt++){
        long row = rowBase + wm + mt*16 + (lane >> 2);
        int b = (int)(row >> 10);
        int pos = (int)(row & 1023);
        if (ccb < 512){
            const float sc = 0.125f;
            if (rothalf){
                #pragma unroll
                for (int nt = 0; nt < 2; nt++){
                    int cc0 = ccb + nt*8 + 2*(lane & 3);
                    int d0  = nt*8 + 2*(lane & 3);
                    #pragma unroll
                    for (int half = 0; half < 2; half++){
                        long rr = row + half*8;
                        int pp = pos + half*8;
                        float a0 = acc[mt][nt][half*2+0]*sc, b0 = acc[mt][nt+2][half*2+0]*sc;
                        float a1 = acc[mt][nt][half*2+1]*sc, b1 = acc[mt][nt+2][half*2+1]*sc;
                        float c0 = rotc[pp*16 + d0],   s0 = rots[pp*16 + d0];
                        float c1 = rotc[pp*16 + d0+1], s1 = rots[pp*16 + d0+1];
                        uint32_t hp, lp;
                        splitpack(a0*c0 - b0*s0, a1*c1 - b1*s1, hp, lp);
                        *(uint32_t*)(QH + rr*DD + cc0) = hp;
                        *(uint32_t*)(QL + rr*DD + cc0) = lp;
                        splitpack(a0*s0 + b0*c0, a1*s1 + b1*c1, hp, lp);
                        *(uint32_t*)(QH + rr*DD + cc0 + 16) = hp;
                        *(uint32_t*)(QL + rr*DD + cc0 + 16) = lp;
                    }
                }
            } else {
                #pragma unroll
                for (int nt = 0; nt < 4; nt++){
                    int cc0 = ccb + nt*8 + 2*(lane & 3);
                    uint32_t hp, lp;
                    splitpack(acc[mt][nt][0]*sc, acc[mt][nt][1]*sc, hp, lp);
                    *(uint32_t*)(QH + row*DD + cc0) = hp;
                    *(uint32_t*)(QL + row*DD + cc0) = lp;
                    splitpack(acc[mt][nt][2]*sc, acc[mt][nt][3]*sc, hp, lp);
                    *(uint32_t*)(QH + (row+8)*DD + cc0) = hp;
                    *(uint32_t*)(QL + (row+8)*DD + cc0) = lp;
                }
            }
        } else if (ccb < 576){
            if (rothalf){
                #pragma unroll
                for (int nt = 0; nt < 2; nt++){
                    int d0 = nt*8 + 2*(lane & 3);
                    #pragma unroll
                    for (int half = 0; half < 2; half++){
                        int pp = pos + half*8;
                        long ko = ((long)b*PADS + pp + 1)*DH;
                        float a0 = acc[mt][nt][half*2+0], b0 = acc[mt][nt+2][half*2+0];
                        float a1 = acc[mt][nt][half*2+1], b1 = acc[mt][nt+2][half*2+1];
                        float c0 = rotc[pp*16 + d0],   s0 = rots[pp*16 + d0];
                        float c1 = rotc[pp*16 + d0+1], s1 = rots[pp*16 + d0+1];
                        uint32_t hp, lp;
                        splitpack(a0*c0 - b0*s0, a1*c1 - b1*s1, hp, lp);
                        *(uint32_t*)(KHp + ko + d0) = hp;
                        *(uint32_t*)(KLp + ko + d0) = lp;
                        splitpack(a0*s0 + b0*c0, a1*s1 + b1*c1, hp, lp);
                        *(uint32_t*)(KHp + ko + d0 + 16) = hp;
                        *(uint32_t*)(KLp + ko + d0 + 16) = lp;
                    }
                }
            } else {
                #pragma unroll
                for (int nt = 0; nt < 4; nt++){
                    int d0 = 32 + nt*8 + 2*(lane & 3);
                    #pragma unroll
                    for (int half = 0; half < 2; half++){
                        long ko = ((long)b*PADS + pos + half*8 + 1)*DH;
                        uint32_t hp, lp;
                        splitpack(acc[mt][nt][half*2+0], acc[mt][nt][half*2+1], hp, lp);
                        *(uint32_t*)(KHp + ko + d0) = hp;
                        *(uint32_t*)(KLp + ko + d0) = lp;
                    }
                }
            }
        } else {
            #pragma unroll
            for (int nt = 0; nt < 4; nt++){
                int d0 = (ccb - 576) + nt*8 + 2*(lane & 3);
                #pragma unroll
                for (int e = 0; e < 4; e++){
                    int d = d0 + (e & 1);
                    long j = pos + (e >> 1)*8 + 1;
                    unsigned short h, l;
                    split_bf16(acc[mt][nt][e], h, l);
                    VTH[((long)b*DH + d)*PW + j] = __ushort_as_bfloat16(h);
                    VTL[((long)b*DH + d)*PW + j] = __ushort_as_bfloat16(l);
                }
            }
        }
    }
}
#undef DLOAD

// ============================================================================
//  Fused flash attention (single-buffer, split K/V waits — round-11 version)
//  smem: Q 16K | K 16K | V 16K | bias 4K  = 53248  (4 CTAs/SM)
// ============================================================================
#define FSM_Q  0
#define FSM_K  16384
#define FSM_V  32768
#define FSM_B  49152
#define FSM_TOT (49152 + 4096)

__global__ __launch_bounds__(128) void flash_attn(const __nv_bfloat16* __restrict__ Qh,
                                                  const __nv_bfloat16* __restrict__ Ql,
                                                  const __nv_bfloat16* __restrict__ KHp,
                                                  const __nv_bfloat16* __restrict__ KLp,
                                                  const __nv_bfloat16* __restrict__ VTHp,
                                                  const __nv_bfloat16* __restrict__ VTLp,
                                                  const float* __restrict__ bias_tab,
                                                  __nv_bfloat16* __restrict__ OH,
                                                  __nv_bfloat16* __restrict__ OL,
                                                  int nkv, int cb){
    extern __shared__ __align__(16) char sm[];
    uint32_t sb = smem_u32(sm);
    int t = threadIdx.x, lane = t & 31, warp = t >> 5;
    int bh = blockIdx.y, b = bh >> 3, h = bh & 7;
    int i0 = blockIdx.x * 64;

    {
        const __nv_bfloat16* qh = Qh + ((long)(b*NQ + i0))*DD + h*DH;
        const __nv_bfloat16* ql = Ql + ((long)(b*NQ + i0))*DD + h*DH;
        for (int i = t; i < 512; i += 128){
            int r = i >> 3, c = i & 7;
            cpg(sb + FSM_Q        + SWOFF8(r,c), qh + (long)r*DD + c*8);
            cpg(sb + FSM_Q + 8192 + SWOFF8(r,c), ql + (long)r*DD + c*8);
        }
        CP_COMMIT();
    }
    if (cb){
        float* bsm = (float*)(sm + FSM_B);
        for (int i = t; i < 1024; i += 128) bsm[i] = bias_tab[h*1024 + i];
    }
    CP_WAIT0();
    __syncthreads();

    uint32_t qfh[4][4], qfl[4][4];
    #pragma unroll
    for (int s = 0; s < 4; s++){
        int r = warp*16 + (lane & 15);
        int cl = 2*s + (lane >> 4);
        ldsm4(qfh[s], sb + FSM_Q + SWOFF8(r, cl));
        ldsm4(qfl[s], sb + FSM_Q + 8192 + SWOFF8(r, cl));
    }

    float o[8][4];
    #pragma unroll
    for (int i=0;i<8;i++)
        #pragma unroll
        for (int e=0;e<4;e++) o[i][e] = 0.f;
    float mx0 = -3.0e38f, mx1 = -3.0e38f, sum0 = 0.f, sum1 = 0.f;

    int jt_max = (nkv - 1) >> 6;
    if (cb){ int jm = (i0 + 64) >> 6; if (jm < jt_max) jt_max = jm; }
    const __nv_bfloat16* kh = KHp + (long)b*PADS*DH;
    const __nv_bfloat16* kl = KLp + (long)b*PADS*DH;
    const __nv_bfloat16* vh = VTHp + (long)b*DH*PW;
    const __nv_bfloat16* vl = VTLp + (long)b*DH*PW;
    const float* bsm = (const float*)(sm + FSM_B);

    for (int jt = 0; jt <= jt_max; jt++){
        for (int i = t; i < 512; i += 128){
            int r = i >> 3, c = i & 7;
            cpg(sb + FSM_K        + SWOFF8(r,c), kh + ((long)(jt*64 + r))*DH + c*8);
            cpg(sb + FSM_K + 8192 + SWOFF8(r,c), kl + ((long)(jt*64 + r))*DH + c*8);
        }
        CP_COMMIT();
        for (int i = t; i < 512; i += 128){
            int r = i >> 3, c = i & 7;
            cpg(sb + FSM_V        + SWOFF8(r,c), vh + (long)r*PW + jt*64 + c*8);
            cpg(sb + FSM_V + 8192 + SWOFF8(r,c), vl + (long)r*PW + jt*64 + c*8);
        }
        CP_COMMIT();
        CP_WAIT1();
        __syncthreads();

        float sacc[8][4];
        #pragma unroll
        for (int i=0;i<8;i++)
            #pragma unroll
            for (int e=0;e<4;e++) sacc[i][e] = 0.f;
        #pragma unroll
        for (int s = 0; s < 4; s++){
            uint32_t bhf[8][2], blf[8][2];
            #pragma unroll
            for (int g = 0; g < 4; g++){
                int r = g*16 + (lane & 7) + ((lane >> 4) << 3);
                int cl = 2*s + ((lane >> 3) & 1);
                uint32_t tmp[4];
                ldsm4(tmp, sb + FSM_K + SWOFF8(r, cl));
                bhf[2*g][0]=tmp[0]; bhf[2*g][1]=tmp[1]; bhf[2*g+1][0]=tmp[2]; bhf[2*g+1][1]=tmp[3];
                ldsm4(tmp, sb + FSM_K + 8192 + SWOFF8(r, cl));
                blf[2*g][0]=tmp[0]; blf[2*g][1]=tmp[1]; blf[2*g+1][0]=tmp[2]; blf[2*g+1][1]=tmp[3];
            }
            #pragma unroll
            for (int nt = 0; nt < 8; nt++){
                mma16816(sacc[nt], qfh[s], bhf[nt][0], bhf[nt][1]);
                mma16816(sacc[nt], qfh[s], blf[nt][0], blf[nt][1]);
                mma16816(sacc[nt], qfl[s], bhf[nt][0], bhf[nt][1]);
            }
        }

        int ibase = i0 + warp*16 + (lane >> 2);
        int jbase = jt*64 + 2*(lane & 3);
        float tmx0 = -3.0e38f, tmx1 = -3.0e38f;
        #pragma unroll
        for (int nt = 0; nt < 8; nt++){
            #pragma unroll
            for (int e = 0; e < 4; e++){
                int i = ibase + ((e >> 1) << 3);
                int j = jbase + nt*8 + (e & 1);
                float s = sacc[nt][e];
                if (cb){
                    int nn = i - j; if (nn < 0) nn = 0;
                    s += bsm[nn];
                    if (j > i + 1) s = -1e30f;
                }
                if (j >= nkv) s = -1e30f;
                sacc[nt][e] = s;
                if (e < 2) tmx0 = fmaxf(tmx0, s); else tmx1 = fmaxf(tmx1, s);
            }
        }
        tmx0 = fmaxf(tmx0, __shfl_xor_sync(0xffffffffu, tmx0, 1));
        tmx0 = fmaxf(tmx0, __shfl_xor_sync(0xffffffffu, tmx0, 2));
        tmx1 = fmaxf(tmx1, __shfl_xor_sync(0xffffffffu, tmx1, 1));
        tmx1 = fmaxf(tmx1, __shfl_xor_sync(0xffffffffu, tmx1, 2));
        float nmx0 = fmaxf(mx0, tmx0), nmx1 = fmaxf(mx1, tmx1);
        float al0 = expf(mx0 - nmx0), al1 = expf(mx1 - nmx1);
        mx0 = nmx0; mx1 = nmx1;
        sum0 *= al0; sum1 *= al1;
        #pragma unroll
        for (int nt = 0; nt < 8; nt++){
            o[nt][0] *= al0; o[nt][1] *= al0;
            o[nt][2] *= al1; o[nt][3] *= al1;
        }

        CP_WAIT0();
        __syncthreads();

        float ts0 = 0.f, ts1 = 0.f;
        #pragma unroll
        for (int kg = 0; kg < 4; kg++){
            uint32_t phf[4], plf[4];
            #pragma unroll
            for (int half = 0; half < 2; half++){
                int nt = 2*kg + half;
                unsigned short hb[4], lb[4];
                #pragma unroll
                for (int e = 0; e < 4; e++){
                    float pe = expf(sacc[nt][e] - ((e < 2) ? mx0 : mx1));
                    if (e < 2) ts0 += pe; else ts1 += pe;
                    split_bf16(pe, hb[e], lb[e]);
                }
                phf[2*half+0] = (uint32_t)hb[0] | ((uint32_t)hb[1] << 16);
                phf[2*half+1] = (uint32_t)hb[2] | ((uint32_t)hb[3] << 16);
                plf[2*half+0] = (uint32_t)lb[0] | ((uint32_t)lb[1] << 16);
                plf[2*half+1] = (uint32_t)lb[2] | ((uint32_t)lb[3] << 16);
            }
            uint32_t vhf[8][2], vlf[8][2];
            #pragma unroll
            for (int g = 0; g < 4; g++){
                int r = g*16 + (lane & 7) + ((lane >> 4) << 3);
                int cl = 2*kg + ((lane >> 3) & 1);
                uint32_t tmp[4];
                ldsm4(tmp, sb + FSM_V + SWOFF8(r, cl));
                vhf[2*g][0]=tmp[0]; vhf[2*g][1]=tmp[1]; vhf[2*g+1][0]=tmp[2]; vhf[2*g+1][1]=tmp[3];
                ldsm4(tmp, sb + FSM_V + 8192 + SWOFF8(r, cl));
                vlf[2*g][0]=tmp[0]; vlf[2*g][1]=tmp[1]; vlf[2*g+1][0]=tmp[2]; vlf[2*g+1][1]=tmp[3];
            }
            #pragma unroll
            for (int nt = 0; nt < 8; nt++){
                mma16816(o[nt], phf, vhf[nt][0], vhf[nt][1]);
                mma16816(o[nt], phf, vlf[nt][0], vlf[nt][1]);
                mma16816(o[nt], plf, vhf[nt][0], vhf[nt][1]);
            }
        }
        ts0 += __shfl_xor_sync(0xffffffffu, ts0, 1);
        ts0 += __shfl_xor_sync(0xffffffffu, ts0, 2);
        ts1 += __shfl_xor_sync(0xffffffffu, ts1, 1);
        ts1 += __shfl_xor_sync(0xffffffffu, ts1, 2);
        sum0 += ts0; sum1 += ts1;
        __syncthreads();
    }

    float inv0 = 1.f / sum0, inv1 = 1.f / sum1;
    long r0 = (long)b*NQ + i0 + warp*16 + (lane >> 2);
    #pragma unroll
    for (int nt = 0; nt < 8; nt++){
        int c = nt*8 + 2*(lane & 3);
        uint32_t hp, lp;
        splitpack(o[nt][0]*inv0, o[nt][1]*inv0, hp, lp);
        *(uint32_t*)(OH + r0*DD + h*DH + c) = hp;
        *(uint32_t*)(OL + r0*DD + h*DH + c) = lp;
        splitpack(o[nt][2]*inv1, o[nt][3]*inv1, hp, lp);
        *(uint32_t*)(OH + (r0+8)*DD + h*DH + c) = hp;
        *(uint32_t*)(OL + (r0+8)*DD + h*DH + c) = lp;
    }
}

// ---------------- orchestration --------------------------------------------
extern "C" void kernel_launch(void* const* d_in, const int* in_sizes, int n_in,
                              void* d_out, int out_size){
    const float* x_in    = (const float*)d_in[0];
    const float* ctx     = (const float*)d_in[1];
    const float* rel_emb = (const float*)d_in[2];
    const float* sa_ng   = (const float*)d_in[3];
    const float* sa_wq   = (const float*)d_in[4];
    const float* sa_wkv  = (const float*)d_in[5];
    const float* sa_null = (const float*)d_in[6];
    const float* sa_wo   = (const float*)d_in[7];
    const float* sa_og   = (const float*)d_in[8];
    const float* ca_ng   = (const float*)d_in[9];
    const float* ca_cg   = (const float*)d_in[10];
    const float* ca_wq   = (const float*)d_in[11];
    const float* ca_wkv  = (const float*)d_in[12];
    const float* ca_null = (const float*)d_in[13];
    const float* ca_wo   = (const float*)d_in[14];
    const float* ca_og   = (const float*)d_in[15];
    const float* ff_ng   = (const float*)d_in[16];
    const float* ff_w1   = (const float*)d_in[17];
    const float* ff_w2   = (const float*)d_in[18];
    const float* normg   = (const float*)d_in[19];
    float* out = (float*)d_out;

    cudaFuncSetAttribute(tgemm3,        cudaFuncAttributeMaxDynamicSharedMemorySize, 65536);
    cudaFuncSetAttribute(tgemm3_glu,    cudaFuncAttributeMaxDynamicSharedMemorySize, 65536);
    cudaFuncSetAttribute(tgemm3_qsplit, cudaFuncAttributeMaxDynamicSharedMemorySize, 65536);
    cudaFuncSetAttribute(tgemm3_kv,     cudaFuncAttributeMaxDynamicSharedMemorySize, 65536);
    cudaFuncSetAttribute(tgemm3_qkv,    cudaFuncAttributeMaxDynamicSharedMemorySize, 65536);
    cudaFuncSetAttribute(flash_attn,    cudaFuncAttributeMaxDynamicSharedMemorySize, FSM_TOT);

    float *X,*QO,*BT,*RC,*RS;
    __nv_bfloat16 *AH,*AL,*GH,*GL,*BH,*BL,*KH,*KL,*VTH,*VTL;
    cudaGetSymbolAddress((void**)&X,    g_x);
    cudaGetSymbolAddress((void**)&QO,   g_q);
    cudaGetSymbolAddress((void**)&BT,   g_bias);
    cudaGetSymbolAddress((void**)&RC,   g_rotc);
    cudaGetSymbolAddress((void**)&RS,   g_rots);
    cudaGetSymbolAddress((void**)&AH,   g_AH);
    cudaGetSymbolAddress((void**)&AL,   g_AL);
    cudaGetSymbolAddress((void**)&GH,   g_GH);
    cudaGetSymbolAddress((void**)&GL,   g_GL);
    cudaGetSymbolAddress((void**)&BH,   g_BH);
    cudaGetSymbolAddress((void**)&BL,   g_BL);
    cudaGetSymbolAddress((void**)&KH,   g_KH);
    cudaGetSymbolAddress((void**)&KL,   g_KL);
    cudaGetSymbolAddress((void**)&VTH,  g_VTH);
    cudaGetSymbolAddress((void**)&VTL,  g_VTL);
    // activation split regions inside g_AH/g_AL (8M elems each):
    __nv_bfloat16 *XQH = AH,                         *XQL = AL;                        // [0,2M)  LN(x) split
    __nv_bfloat16 *ATH = AH + (size_t)2*1024*1024,   *ATL = AL + (size_t)2*1024*1024;  // [2M,4M) ATT split
    __nv_bfloat16 *CXH = AH + (size_t)4*1024*1024,   *CXL = AL + (size_t)4*1024*1024;  // [4M,5M) ctx split
    __nv_bfloat16 *QSH = AH + (size_t)5*1024*1024,   *QSL = AL + (size_t)5*1024*1024;  // [5M,7M) Q split

    copy_kernel<<<512, 256>>>(x_in, X, RR*DD);
    bias_tab_kernel<<<4, 256>>>(rel_emb, BT);
    rot_tab_kernel<<<64, 256>>>(RC, RS);
    convBT_all<<<LL*4192, 256>>>(sa_wq, sa_wkv, sa_wo, ca_wq, ca_wkv, ca_wo,
                                 ff_w1, ff_w2, BH, BL);

    for (int l = 0; l < LL; l++){
        const __nv_bfloat16 *WBH = BH + (size_t)l*WL, *WBL = BL + (size_t)l*WL;

        // ---------------- self-attention (fully fused QKV prep) -----------
        ln_split_w<<<RR/8, 256>>>(X, sa_ng + l*DD, XQH, XQL, DD);
        nullkv_kernel<<<BB, 64>>>(sa_null + l*128, KH, KL, VTH, VTL);
        tgemm3_qkv<<<dim3(QW/128, RR/128), 256, 65536>>>(XQH, XQL, WBH + WOF_WQ, WBL + WOF_WQ,
                                                         QSH, QSL, KH, KL, VTH, VTL, RC, RS, RR, QW, DD);
        flash_attn<<<dim3(NQ/64, BB*HH), 128, FSM_TOT>>>(QSH, QSL, KH, KL, VTH, VTL, BT, ATH, ATL, NQ+1, 1);
        tgemm3<<<dim3(DD/128, RR/128), 256, 65536>>>(ATH, ATL, WBH + WOF_WO, WBL + WOF_WO, QO, RR, DD, DD, 0);
        ln_res_split_w<<<RR/8, 256>>>(QO, sa_og + l*DD, X, ca_ng + l*DD, XQH, XQL);

        // ---------------- cross-attention ----------------
        ln_split_w<<<CR/8, 256>>>(ctx, ca_cg + l*PP, CXH, CXL, PP);
        nullkv_kernel<<<BB, 64>>>(ca_null + l*128, KH, KL, VTH, VTL);
        tgemm3_kv<<<dim3(1, CR/128), 256, 65536>>>(CXH, CXL, WBH + WOF_CWKV, WBL + WOF_CWKV,
                                                   KH, KL, VTH, VTL, CR, 128, PP);
        tgemm3_qsplit<<<dim3(DD/128, RR/128), 256, 65536>>>(XQH, XQL, WBH + WOF_CWQ, WBL + WOF_CWQ,
                                                            QSH, QSL, RR, DD, DD);
        flash_attn<<<dim3(NQ/64, BB*HH), 128, FSM_TOT>>>(QSH, QSL, KH, KL, VTH, VTL, BT, ATH, ATL, MM+1, 0);
        tgemm3<<<dim3(DD/128, RR/128), 256, 65536>>>(ATH, ATL, WBH + WOF_CWO, WBL + WOF_CWO, QO, RR, DD, DD, 0);
        ln_res_split_w<<<RR/8, 256>>>(QO, ca_og + l*DD, X, ff_ng + l*DD, XQH, XQL);

        // ---------------- feed-forward (GLU fused into w1 GEMM) ------------
        tgemm3_glu<<<dim3((2*FFI)/128, RR/128), 256, 65536>>>(XQH, XQL, WBH + WOF_W1, WBL + WOF_W1,
                                                              GH, GL, RR, 2*FFI, DD);
        tgemm3<<<dim3(DD/128, RR/128), 256, 65536>>>(GH, GL, WBH + WOF_W2, WBL + WOF_W2, X, RR, DD, FFI, 1);
    }

    final_ln_w<<<RR/8, 256>>>(X, normg, out);
}